// round 2
// baseline (speedup 1.0000x reference)
#include <cuda_runtime.h>
#include <math.h>

#define BB 4
#define LL 1025
#define NT 1361
#define DD 512
#define HH 8
#define DKK 64
#define DFF 2048
#define SW 1408               // padded score row width (22*64)
#define MROWS (BB*NT)         // 5444

// ---------------- scratch (static device allocations) ----------------
__device__ float g_emb[BB*LL*DD];
__device__ float g_d0 [BB*LL*128];
__device__ float g_cc [BB*336*128];
__device__ float g_pyr[BB*336*DD];
__device__ float g_seq[BB*NT*DD];
__device__ float g_q  [BB*NT*DD];
__device__ float g_k  [BB*NT*DD];
__device__ float g_v  [BB*NT*DD];
__device__ float g_o  [BB*NT*DD];
__device__ float g_tmp[BB*NT*DD];
__device__ float g_ffn[BB*NT*DFF];
__device__ float g_scores[(size_t)BB*HH*NT*SW];   // ~245 MB

// ---------------- mask (analytic) ----------------
__device__ __forceinline__ bool pyr_allowed(int i, int j) {
    if (j >= NT) return false;
    const int S1 = 1025, S2 = 1281, S3 = 1345;
    int li = (i < S1) ? 0 : (i < S2) ? 1 : (i < S3) ? 2 : 3;
    int lj = (j < S1) ? 0 : (j < S2) ? 1 : (j < S3) ? 2 : 3;
    if (li == lj) { int d = i - j; return (d <= 2) && (d >= -2); }
    int dl = li - lj;
    if (dl != 1 && dl != -1) return false;
    int p  = (dl == 1) ? i : j;
    int c  = (dl == 1) ? j : i;
    int lp = (dl == 1) ? li : lj;
    const int starts[5] = {0, 1025, 1281, 1345, 1361};
    int s  = starts[lp];
    int ps = starts[lp-1];
    int sz = starts[lp+1] - s;
    int qq = p - s;
    int lo = ps + qq * 4;
    int hi = (qq == sz - 1) ? s : (ps + (qq + 1) * 4);
    return (c >= lo) && (c < hi);
}

// ---------------- embedding ----------------
__global__ void embed_kernel(const float* __restrict__ x_enc,
                             const float* __restrict__ xme,
                             const float* __restrict__ xmd,
                             const float* __restrict__ tw,
                             const float* __restrict__ tb,
                             const float* __restrict__ tempw,
                             const float* __restrict__ tempb) {
    int t = blockIdx.x, b = blockIdx.y;
    __shared__ float xv[3][7];
    __shared__ float xm[4];
    int tid = threadIdx.x;   // 128
    if (tid < 21) {
        int k = tid / 7, i = tid % 7;
        int r = t - 1 + k;
        int rr = (r + 1025) % 1025;
        float val = 0.f;
        if (rr < 1024) val = x_enc[((size_t)b*1024 + rr)*7 + i];
        xv[k][i] = val;
    }
    if (tid >= 32 && tid < 36) {
        int m = tid - 32;
        xm[m] = (t < 1024) ? xme[((size_t)b*1024 + t)*4 + m]
                           : xmd[((size_t)b*96)*4 + m];
    }
    __syncthreads();
    for (int d = tid; d < DD; d += 128) {
        float acc = tb[d];
        #pragma unroll
        for (int i = 0; i < 7; i++)
            #pragma unroll
            for (int k = 0; k < 3; k++)
                acc += xv[k][i] * tw[(d*7 + i)*3 + k];
        acc += tempb[d];
        #pragma unroll
        for (int m = 0; m < 4; m++) acc += xm[m] * tempw[m*DD + d];
        int m2 = d & ~1;
        float div = expf(-9.210340371976184f / 512.0f * (float)m2);
        float arg = (float)t * div;
        acc += (d & 1) ? cosf(arg) : sinf(arg);
        g_emb[((size_t)b*LL + t)*DD + d] = acc;
    }
}

// ---------------- generic SGEMM: C = A(MxK) @ B(KxN) [+bias][+gelu] ----------------
__device__ __forceinline__ float gelu_exact(float x) {
    return 0.5f * x * (1.0f + erff(x * 0.70710678118654752f));
}

template<int ACT>  // 0=none, 1=gelu
__global__ __launch_bounds__(256)
void sgemm_kernel(const float* __restrict__ A, const float* __restrict__ Bm,
                  const float* __restrict__ bias, float* __restrict__ C,
                  int M, int N, int K) {
    __shared__ float As[8][128];
    __shared__ float Bs[8][128];
    int tid = threadIdx.x;
    int bx = blockIdx.x, by = blockIdx.y;
    int tx = tid & 15, ty = tid >> 4;
    float acc[8][8];
    #pragma unroll
    for (int i = 0; i < 8; i++)
        #pragma unroll
        for (int j = 0; j < 8; j++) acc[i][j] = 0.f;

    int ar = tid >> 1, ac = (tid & 1) * 4;
    int br = tid >> 5, bc = (tid & 31) * 4;
    int arow = by*128 + ar;
    const float* Ap = A + (size_t)arow * K;
    const float* Bp = Bm + bx*128;
    bool avalid = (arow < M);

    for (int k0 = 0; k0 < K; k0 += 8) {
        float4 a4 = avalid ? *(const float4*)(Ap + k0 + ac) : make_float4(0,0,0,0);
        As[ac+0][ar] = a4.x; As[ac+1][ar] = a4.y; As[ac+2][ar] = a4.z; As[ac+3][ar] = a4.w;
        float4 b4 = *(const float4*)(Bp + (size_t)(k0 + br)*N + bc);
        *(float4*)&Bs[br][bc] = b4;
        __syncthreads();
        #pragma unroll
        for (int k = 0; k < 8; k++) {
            float ra[8], rb[8];
            *(float4*)&ra[0] = *(const float4*)&As[k][ty*8];
            *(float4*)&ra[4] = *(const float4*)&As[k][ty*8 + 4];
            *(float4*)&rb[0] = *(const float4*)&Bs[k][tx*8];
            *(float4*)&rb[4] = *(const float4*)&Bs[k][tx*8 + 4];
            #pragma unroll
            for (int i = 0; i < 8; i++)
                #pragma unroll
                for (int j = 0; j < 8; j++) acc[i][j] += ra[i]*rb[j];
        }
        __syncthreads();
    }
    #pragma unroll
    for (int i = 0; i < 8; i++) {
        int row = by*128 + ty*8 + i;
        if (row >= M) break;
        #pragma unroll
        for (int j = 0; j < 8; j += 4) {
            int col = bx*128 + tx*8 + j;
            float4 v;
            v.x = acc[i][j]; v.y = acc[i][j+1]; v.z = acc[i][j+2]; v.w = acc[i][j+3];
            if (bias) { v.x += bias[col]; v.y += bias[col+1]; v.z += bias[col+2]; v.w += bias[col+3]; }
            if (ACT == 1) { v.x = gelu_exact(v.x); v.y = gelu_exact(v.y); v.z = gelu_exact(v.z); v.w = gelu_exact(v.w); }
            *(float4*)&C[(size_t)row*N + col] = v;
        }
    }
}

// ---------------- conv (stride-4, kernel-4, ELU) ----------------
__global__ void conv_kernel(const float* __restrict__ in, int ibs, int inOff,
                            const float* __restrict__ w, const float* __restrict__ bias,
                            float* __restrict__ out, int outOff) {
    int t = blockIdx.x, b = blockIdx.y;
    int tid = threadIdx.x;   // 128 (= oc)
    __shared__ float si[512];
    const float* ip = in + (size_t)(b*ibs + inOff + 4*t) * 128;
    #pragma unroll
    for (int k = 0; k < 4; k++) si[k*128 + tid] = ip[k*128 + tid];
    __syncthreads();
    float acc = bias[tid];
    #pragma unroll 4
    for (int ic = 0; ic < 128; ic++) {
        float4 w4 = *(const float4*)&w[((size_t)tid*128 + ic)*4];
        acc += si[ic]*w4.x + si[128+ic]*w4.y + si[256+ic]*w4.z + si[384+ic]*w4.w;
    }
    acc = (acc > 0.f) ? acc : expm1f(acc);
    out[(size_t)(b*336 + outOff + t)*128 + tid] = acc;
}

// ---------------- layernorm core (512 wide, 256 threads) ----------------
__device__ __forceinline__ void ln_core(const float* __restrict__ x0,
                                        const float* __restrict__ x1,
                                        const float* __restrict__ sc,
                                        const float* __restrict__ bb,
                                        float* __restrict__ out) {
    __shared__ float red[8];
    int tid = threadIdx.x;
    float v0 = x0[tid]       + (x1 ? x1[tid]       : 0.f);
    float v1 = x0[tid + 256] + (x1 ? x1[tid + 256] : 0.f);
    float sum = v0 + v1;
    #pragma unroll
    for (int o = 16; o; o >>= 1) sum += __shfl_xor_sync(0xffffffffu, sum, o);
    if ((tid & 31) == 0) red[tid >> 5] = sum;
    __syncthreads();
    float tot = 0.f;
    #pragma unroll
    for (int w = 0; w < 8; w++) tot += red[w];
    float mean = tot * (1.0f/512.0f);
    __syncthreads();
    float d0 = v0 - mean, d1 = v1 - mean;
    float sq = d0*d0 + d1*d1;
    #pragma unroll
    for (int o = 16; o; o >>= 1) sq += __shfl_xor_sync(0xffffffffu, sq, o);
    if ((tid & 31) == 0) red[tid >> 5] = sq;
    __syncthreads();
    float vtot = 0.f;
    #pragma unroll
    for (int w = 0; w < 8; w++) vtot += red[w];
    float inv = rsqrtf(vtot * (1.0f/512.0f) + 1e-5f);
    out[tid]       = d0 * inv * sc[tid]       + bb[tid];
    out[tid + 256] = d1 * inv * sc[tid + 256] + bb[tid + 256];
}

__global__ void concat_ln_kernel(const float* __restrict__ sc, const float* __restrict__ bb) {
    int row = blockIdx.x;            // 0..5443
    int b = row / NT, n = row % NT;
    const float* src = (n < LL) ? &g_emb[((size_t)b*LL + n)*DD]
                                : &g_pyr[((size_t)b*336 + (n - LL))*DD];
    ln_core(src, nullptr, sc, bb, &g_seq[(size_t)row*DD]);
}

__global__ void add_ln_kernel(const float* __restrict__ sc, const float* __restrict__ bb) {
    size_t row = blockIdx.x;
    ln_core(&g_seq[row*DD], &g_tmp[row*DD], sc, bb, &g_seq[row*DD]);
}

// ---------------- attention scores (QK^T, masked, scaled) ----------------
__global__ __launch_bounds__(256)
void score_kernel() {
    int bh = blockIdx.z;  int b = bh >> 3, h = bh & 7;
    int i0 = blockIdx.y * 64, j0 = blockIdx.x * 64;
    __shared__ float Qs[64][65];
    __shared__ float Ks[64][65];
    int tid = threadIdx.x;
    int lr = tid >> 4, lc = (tid & 15) * 4;
    const float* qb = g_q + ((size_t)b*NT + i0)*DD + h*64;
    const float* kb = g_k + ((size_t)b*NT + j0)*DD + h*64;
    #pragma unroll
    for (int rr = 0; rr < 64; rr += 16) {
        int r = lr + rr;
        float4 qv = (i0 + r < NT) ? *(const float4*)(qb + (size_t)r*DD + lc) : make_float4(0,0,0,0);
        Qs[r][lc+0] = qv.x; Qs[r][lc+1] = qv.y; Qs[r][lc+2] = qv.z; Qs[r][lc+3] = qv.w;
        float4 kv = (j0 + r < NT) ? *(const float4*)(kb + (size_t)r*DD + lc) : make_float4(0,0,0,0);
        Ks[r][lc+0] = kv.x; Ks[r][lc+1] = kv.y; Ks[r][lc+2] = kv.z; Ks[r][lc+3] = kv.w;
    }
    __syncthreads();
    int tx = tid & 15, ty = tid >> 4;
    float acc[4][4];
    #pragma unroll
    for (int i = 0; i < 4; i++)
        #pragma unroll
        for (int j = 0; j < 4; j++) acc[i][j] = 0.f;
    #pragma unroll 8
    for (int kk = 0; kk < 64; kk++) {
        float ra[4], rb[4];
        #pragma unroll
        for (int i = 0; i < 4; i++) ra[i] = Qs[ty*4 + i][kk];
        #pragma unroll
        for (int j = 0; j < 4; j++) rb[j] = Ks[tx*4 + j][kk];
        #pragma unroll
        for (int i = 0; i < 4; i++)
            #pragma unroll
            for (int j = 0; j < 4; j++) acc[i][j] += ra[i]*rb[j];
    }
    #pragma unroll
    for (int i = 0; i < 4; i++) {
        int gi = i0 + ty*4 + i;
        if (gi >= NT) break;
        #pragma unroll
        for (int j = 0; j < 4; j++) {
            int gj = j0 + tx*4 + j;
            float val = pyr_allowed(gi, gj) ? acc[i][j] * 0.125f : -1e9f;
            g_scores[((size_t)bh*NT + gi)*SW + gj] = val;
        }
    }
}

// ---------------- softmax over padded rows ----------------
__global__ void softmax_kernel() {
    size_t row = blockIdx.x;            // 32*NT rows
    float* p = &g_scores[row * SW];
    int tid = threadIdx.x;              // 128
    float vals[11];
    float mx = -1e30f;
    #pragma unroll
    for (int it = 0; it < 11; it++) { vals[it] = p[tid + it*128]; mx = fmaxf(mx, vals[it]); }
    __shared__ float red[4];
    #pragma unroll
    for (int o = 16; o; o >>= 1) mx = fmaxf(mx, __shfl_xor_sync(0xffffffffu, mx, o));
    if ((tid & 31) == 0) red[tid >> 5] = mx;
    __syncthreads();
    mx = fmaxf(fmaxf(red[0], red[1]), fmaxf(red[2], red[3]));
    float sum = 0.f;
    #pragma unroll
    for (int it = 0; it < 11; it++) { vals[it] = expf(vals[it] - mx); sum += vals[it]; }
    #pragma unroll
    for (int o = 16; o; o >>= 1) sum += __shfl_xor_sync(0xffffffffu, sum, o);
    __shared__ float red2[4];
    if ((tid & 31) == 0) red2[tid >> 5] = sum;
    __syncthreads();
    float inv = 1.f / (red2[0] + red2[1] + red2[2] + red2[3]);
    #pragma unroll
    for (int it = 0; it < 11; it++) p[tid + it*128] = vals[it] * inv;
}

// ---------------- attn @ V ----------------
__global__ __launch_bounds__(256)
void av_kernel() {
    int bh = blockIdx.y;  int b = bh >> 3, h = bh & 7;
    int i0 = blockIdx.x * 64;
    __shared__ float As[64][65];
    __shared__ float Vs[64][65];
    int tid = threadIdx.x;
    int lr = tid >> 4, lc = (tid & 15) * 4;
    int tx = tid & 15, ty = tid >> 4;
    float acc[4][4];
    #pragma unroll
    for (int i = 0; i < 4; i++)
        #pragma unroll
        for (int j = 0; j < 4; j++) acc[i][j] = 0.f;
    const float* srow = &g_scores[((size_t)bh*NT + i0)*SW];
    for (int j0 = 0; j0 < SW; j0 += 64) {
        #pragma unroll
        for (int rr = 0; rr < 64; rr += 16) {
            int r = lr + rr;
            float4 a4 = (i0 + r < NT) ? *(const float4*)&srow[(size_t)r*SW + j0 + lc] : make_float4(0,0,0,0);
            As[r][lc+0] = a4.x; As[r][lc+1] = a4.y; As[r][lc+2] = a4.z; As[r][lc+3] = a4.w;
            float4 v4 = (j0 + r < NT) ? *(const float4*)&g_v[((size_t)b*NT + j0 + r)*DD + h*64 + lc]
                                      : make_float4(0,0,0,0);
            Vs[r][lc+0] = v4.x; Vs[r][lc+1] = v4.y; Vs[r][lc+2] = v4.z; Vs[r][lc+3] = v4.w;
        }
        __syncthreads();
        #pragma unroll 8
        for (int kk = 0; kk < 64; kk++) {
            float ra[4], rb[4];
            #pragma unroll
            for (int i = 0; i < 4; i++) ra[i] = As[ty*4 + i][kk];
            #pragma unroll
            for (int j = 0; j < 4; j++) rb[j] = Vs[kk][tx*4 + j];
            #pragma unroll
            for (int i = 0; i < 4; i++)
                #pragma unroll
                for (int j = 0; j < 4; j++) acc[i][j] += ra[i]*rb[j];
        }
        __syncthreads();
    }
    #pragma unroll
    for (int i = 0; i < 4; i++) {
        int gi = i0 + ty*4 + i;
        if (gi >= NT) break;
        float4 v;
        v.x = acc[i][0]; v.y = acc[i][1]; v.z = acc[i][2]; v.w = acc[i][3];
        *(float4*)&g_o[((size_t)b*NT + gi)*DD + h*64 + tx*4] = v;
    }
}

// ---------------- gather + prediction head ----------------
__global__ void pred_kernel(const float* __restrict__ pw, float* __restrict__ out) {
    int b = blockIdx.x;
    __shared__ float gv[2048];
    const int rows[4] = {1024, 1280, 1344, 1360};
    int tid = threadIdx.x;   // 672
    for (int r = tid; r < 2048; r += 672) {
        int wch = r >> 9, d = r & 511;
        gv[r] = g_seq[((size_t)b*NT + rows[wch])*DD + d];
    }
    __syncthreads();
    float acc = 0.f;
    for (int r = 0; r < 2048; r++) acc += gv[r] * pw[(size_t)r*672 + tid];
    out[(size_t)b*672 + tid] = acc;
}

// ---------------- host ----------------
static void launch_sgemm(const float* A, const float* Bm, const float* bias,
                         float* C, int M, int N, int K, int act) {
    dim3 grid(N / 128, (M + 127) / 128);
    if (act == 1) sgemm_kernel<1><<<grid, 256>>>(A, Bm, bias, C, M, N, K);
    else          sgemm_kernel<0><<<grid, 256>>>(A, Bm, bias, C, M, N, K);
}

extern "C" void kernel_launch(void* const* d_in, const int* in_sizes, int n_in,
                              void* d_out, int out_size) {
    const float* x_enc   = (const float*)d_in[0];
    const float* xme     = (const float*)d_in[1];
    // d_in[2] = x_dec (unused by the model math)
    const float* xmd     = (const float*)d_in[3];
    const float* token_w = (const float*)d_in[4];
    const float* token_b = (const float*)d_in[5];
    const float* temp_w  = (const float*)d_in[6];
    const float* temp_b  = (const float*)d_in[7];
    const float* down_w  = (const float*)d_in[8];
    const float* down_b  = (const float*)d_in[9];
    const float* conv_w  = (const float*)d_in[10];
    const float* conv_b  = (const float*)d_in[11];
    const float* up_w    = (const float*)d_in[12];
    const float* up_b    = (const float*)d_in[13];
    const float* cln_s   = (const float*)d_in[14];
    const float* cln_b   = (const float*)d_in[15];
    const float* Wq      = (const float*)d_in[16];
    const float* Wk      = (const float*)d_in[17];
    const float* Wv      = (const float*)d_in[18];
    const float* Wo      = (const float*)d_in[19];
    const float* bo      = (const float*)d_in[20];
    const float* ln1_s   = (const float*)d_in[21];
    const float* ln1_b   = (const float*)d_in[22];
    const float* W1      = (const float*)d_in[23];
    const float* b1      = (const float*)d_in[24];
    const float* W2      = (const float*)d_in[25];
    const float* b2      = (const float*)d_in[26];
    const float* ln2_s   = (const float*)d_in[27];
    const float* ln2_b   = (const float*)d_in[28];
    const float* pred_w  = (const float*)d_in[29];

    float *emb, *d0, *cc, *pyr, *seq, *q, *k, *v, *o, *tmp, *ffn;
    cudaGetSymbolAddress((void**)&emb, g_emb);
    cudaGetSymbolAddress((void**)&d0,  g_d0);
    cudaGetSymbolAddress((void**)&cc,  g_cc);
    cudaGetSymbolAddress((void**)&pyr, g_pyr);
    cudaGetSymbolAddress((void**)&seq, g_seq);
    cudaGetSymbolAddress((void**)&q,   g_q);
    cudaGetSymbolAddress((void**)&k,   g_k);
    cudaGetSymbolAddress((void**)&v,   g_v);
    cudaGetSymbolAddress((void**)&o,   g_o);
    cudaGetSymbolAddress((void**)&tmp, g_tmp);
    cudaGetSymbolAddress((void**)&ffn, g_ffn);

    // 1) embedding (token conv + PE + temporal)
    embed_kernel<<<dim3(LL, BB), 128>>>(x_enc, xme, xmd, token_w, token_b, temp_w, temp_b);

    // 2) bottleneck down-projection: (B*L,512)@(512,128)
    launch_sgemm(emb, down_w, down_b, d0, BB*LL, 128, DD, 0);

    // 3) pyramid convs (stride4/k4 + ELU), chained into g_cc rows [0:256|256:320|320:336]
    conv_kernel<<<dim3(256, BB), 128>>>(d0, LL, 0,   conv_w,               conv_b,       cc, 0);
    conv_kernel<<<dim3(64,  BB), 128>>>(cc, 336, 0,  conv_w + 128*128*4,   conv_b + 128, cc, 256);
    conv_kernel<<<dim3(16,  BB), 128>>>(cc, 336, 256,conv_w + 2*128*128*4, conv_b + 256, cc, 320);

    // 4) up-projection: (B*336,128)@(128,512)
    launch_sgemm(cc, up_w, up_b, pyr, BB*336, DD, 128, 0);

    // 5) concat + LayerNorm -> seq
    concat_ln_kernel<<<MROWS, 256>>>(cln_s, cln_b);

    // 6) encoder layers
    for (int i = 0; i < 4; i++) {
        const size_t wofs = (size_t)i * DD * DD;
        launch_sgemm(seq, Wq + wofs, nullptr, q, MROWS, DD, DD, 0);
        launch_sgemm(seq, Wk + wofs, nullptr, k, MROWS, DD, DD, 0);
        launch_sgemm(seq, Wv + wofs, nullptr, v, MROWS, DD, DD, 0);

        score_kernel<<<dim3(SW/64, 22, BB*HH), 256>>>();
        softmax_kernel<<<BB*HH*NT, 128>>>();
        av_kernel<<<dim3(22, BB*HH), 256>>>();

        launch_sgemm(o, Wo + wofs, bo + i*DD, tmp, MROWS, DD, DD, 0);
        add_ln_kernel<<<MROWS, 256>>>(ln1_s + i*DD, ln1_b + i*DD);

        launch_sgemm(seq, W1 + (size_t)i*DD*DFF, b1 + i*DFF, ffn, MROWS, DFF, DD, 1);
        launch_sgemm(ffn, W2 + (size_t)i*DFF*DD, b2 + i*DD, tmp, MROWS, DD, DFF, 0);
        add_ln_kernel<<<MROWS, 256>>>(ln2_s + i*DD, ln2_b + i*DD);
    }

    // 7) gather pyramid nodes of the last step + prediction head
    pred_kernel<<<BB, 672>>>(pred_w, (float*)d_out);
}

// round 3
// speedup vs baseline: 1.5123x; 1.5123x over previous
#include <cuda_runtime.h>
#include <math.h>

#define BB 4
#define LL 1025
#define NT 1361
#define DD 512
#define HH 8
#define DKK 64
#define DFF 2048
#define MROWS (BB*NT)         // 5444

// ---------------- scratch (static device allocations) ----------------
__device__ float g_emb[BB*LL*DD];
__device__ float g_d0 [BB*LL*128];
__device__ float g_cc [BB*336*128];
__device__ float g_pyr[BB*336*DD];
__device__ float g_seq[BB*NT*DD];
__device__ float g_q  [BB*NT*DD];
__device__ float g_k  [BB*NT*DD];
__device__ float g_v  [BB*NT*DD];
__device__ float g_o  [BB*NT*DD];
__device__ float g_tmp[BB*NT*DD];
__device__ float g_ffn[BB*NT*DFF];

// ---------------- embedding ----------------
__global__ void embed_kernel(const float* __restrict__ x_enc,
                             const float* __restrict__ xme,
                             const float* __restrict__ xmd,
                             const float* __restrict__ tw,
                             const float* __restrict__ tb,
                             const float* __restrict__ tempw,
                             const float* __restrict__ tempb) {
    int t = blockIdx.x, b = blockIdx.y;
    __shared__ float xv[3][7];
    __shared__ float xm[4];
    int tid = threadIdx.x;   // 128
    if (tid < 21) {
        int k = tid / 7, i = tid % 7;
        int r = t - 1 + k;
        int rr = (r + 1025) % 1025;
        float val = 0.f;
        if (rr < 1024) val = x_enc[((size_t)b*1024 + rr)*7 + i];
        xv[k][i] = val;
    }
    if (tid >= 32 && tid < 36) {
        int m = tid - 32;
        xm[m] = (t < 1024) ? xme[((size_t)b*1024 + t)*4 + m]
                           : xmd[((size_t)b*96)*4 + m];
    }
    __syncthreads();
    for (int d = tid; d < DD; d += 128) {
        float acc = tb[d];
        #pragma unroll
        for (int i = 0; i < 7; i++)
            #pragma unroll
            for (int k = 0; k < 3; k++)
                acc += xv[k][i] * tw[(d*7 + i)*3 + k];
        acc += tempb[d];
        #pragma unroll
        for (int m = 0; m < 4; m++) acc += xm[m] * tempw[m*DD + d];
        int m2 = d & ~1;
        float div = expf(-9.210340371976184f / 512.0f * (float)m2);
        float arg = (float)t * div;
        acc += (d & 1) ? cosf(arg) : sinf(arg);
        g_emb[((size_t)b*LL + t)*DD + d] = acc;
    }
}

// ---------------- generic SGEMM: C = A(MxK) @ B(KxN) [+bias][+gelu] ----------------
__device__ __forceinline__ float gelu_exact(float x) {
    return 0.5f * x * (1.0f + erff(x * 0.70710678118654752f));
}

template<int ACT>  // 0=none, 1=gelu
__global__ __launch_bounds__(256)
void sgemm_kernel(const float* __restrict__ A, const float* __restrict__ Bm,
                  const float* __restrict__ bias, float* __restrict__ C,
                  int M, int N, int K) {
    __shared__ float As[8][128];
    __shared__ float Bs[8][128];
    int tid = threadIdx.x;
    int bx = blockIdx.x, by = blockIdx.y;
    int tx = tid & 15, ty = tid >> 4;
    float acc[8][8];
    #pragma unroll
    for (int i = 0; i < 8; i++)
        #pragma unroll
        for (int j = 0; j < 8; j++) acc[i][j] = 0.f;

    int ar = tid >> 1, ac = (tid & 1) * 4;
    int br = tid >> 5, bc = (tid & 31) * 4;
    int arow = by*128 + ar;
    const float* Ap = A + (size_t)arow * K;
    const float* Bp = Bm + bx*128;
    bool avalid = (arow < M);

    for (int k0 = 0; k0 < K; k0 += 8) {
        float4 a4 = avalid ? *(const float4*)(Ap + k0 + ac) : make_float4(0,0,0,0);
        As[ac+0][ar] = a4.x; As[ac+1][ar] = a4.y; As[ac+2][ar] = a4.z; As[ac+3][ar] = a4.w;
        float4 b4 = *(const float4*)(Bp + (size_t)(k0 + br)*N + bc);
        *(float4*)&Bs[br][bc] = b4;
        __syncthreads();
        #pragma unroll
        for (int k = 0; k < 8; k++) {
            float ra[8], rb[8];
            *(float4*)&ra[0] = *(const float4*)&As[k][ty*8];
            *(float4*)&ra[4] = *(const float4*)&As[k][ty*8 + 4];
            *(float4*)&rb[0] = *(const float4*)&Bs[k][tx*8];
            *(float4*)&rb[4] = *(const float4*)&Bs[k][tx*8 + 4];
            #pragma unroll
            for (int i = 0; i < 8; i++)
                #pragma unroll
                for (int j = 0; j < 8; j++) acc[i][j] += ra[i]*rb[j];
        }
        __syncthreads();
    }
    #pragma unroll
    for (int i = 0; i < 8; i++) {
        int row = by*128 + ty*8 + i;
        if (row >= M) break;
        #pragma unroll
        for (int j = 0; j < 8; j += 4) {
            int col = bx*128 + tx*8 + j;
            float4 v;
            v.x = acc[i][j]; v.y = acc[i][j+1]; v.z = acc[i][j+2]; v.w = acc[i][j+3];
            if (bias) { v.x += bias[col]; v.y += bias[col+1]; v.z += bias[col+2]; v.w += bias[col+3]; }
            if (ACT == 1) { v.x = gelu_exact(v.x); v.y = gelu_exact(v.y); v.z = gelu_exact(v.z); v.w = gelu_exact(v.w); }
            *(float4*)&C[(size_t)row*N + col] = v;
        }
    }
}

// ---------------- conv (stride-4, kernel-4, ELU) ----------------
__global__ void conv_kernel(const float* __restrict__ in, int ibs, int inOff,
                            const float* __restrict__ w, const float* __restrict__ bias,
                            float* __restrict__ out, int outOff) {
    int t = blockIdx.x, b = blockIdx.y;
    int tid = threadIdx.x;   // 128 (= oc)
    __shared__ float si[512];
    const float* ip = in + (size_t)(b*ibs + inOff + 4*t) * 128;
    #pragma unroll
    for (int k = 0; k < 4; k++) si[k*128 + tid] = ip[k*128 + tid];
    __syncthreads();
    float acc = bias[tid];
    #pragma unroll 4
    for (int ic = 0; ic < 128; ic++) {
        float4 w4 = *(const float4*)&w[((size_t)tid*128 + ic)*4];
        acc += si[ic]*w4.x + si[128+ic]*w4.y + si[256+ic]*w4.z + si[384+ic]*w4.w;
    }
    acc = (acc > 0.f) ? acc : expm1f(acc);
    out[(size_t)(b*336 + outOff + t)*128 + tid] = acc;
}

// ---------------- layernorm core (512 wide, 256 threads) ----------------
__device__ __forceinline__ void ln_core(const float* __restrict__ x0,
                                        const float* __restrict__ x1,
                                        const float* __restrict__ sc,
                                        const float* __restrict__ bb,
                                        float* __restrict__ out) {
    __shared__ float red[8];
    int tid = threadIdx.x;
    float v0 = x0[tid]       + (x1 ? x1[tid]       : 0.f);
    float v1 = x0[tid + 256] + (x1 ? x1[tid + 256] : 0.f);
    float sum = v0 + v1;
    #pragma unroll
    for (int o = 16; o; o >>= 1) sum += __shfl_xor_sync(0xffffffffu, sum, o);
    if ((tid & 31) == 0) red[tid >> 5] = sum;
    __syncthreads();
    float tot = 0.f;
    #pragma unroll
    for (int w = 0; w < 8; w++) tot += red[w];
    float mean = tot * (1.0f/512.0f);
    __syncthreads();
    float d0 = v0 - mean, d1 = v1 - mean;
    float sq = d0*d0 + d1*d1;
    #pragma unroll
    for (int o = 16; o; o >>= 1) sq += __shfl_xor_sync(0xffffffffu, sq, o);
    if ((tid & 31) == 0) red[tid >> 5] = sq;
    __syncthreads();
    float vtot = 0.f;
    #pragma unroll
    for (int w = 0; w < 8; w++) vtot += red[w];
    float inv = rsqrtf(vtot * (1.0f/512.0f) + 1e-5f);
    out[tid]       = d0 * inv * sc[tid]       + bb[tid];
    out[tid + 256] = d1 * inv * sc[tid + 256] + bb[tid + 256];
}

__global__ void concat_ln_kernel(const float* __restrict__ sc, const float* __restrict__ bb) {
    int row = blockIdx.x;            // 0..5443
    int b = row / NT, n = row % NT;
    const float* src = (n < LL) ? &g_emb[((size_t)b*LL + n)*DD]
                                : &g_pyr[((size_t)b*336 + (n - LL))*DD];
    ln_core(src, nullptr, sc, bb, &g_seq[(size_t)row*DD]);
}

__global__ void add_ln_kernel(const float* __restrict__ sc, const float* __restrict__ bb) {
    size_t row = blockIdx.x;
    ln_core(&g_seq[row*DD], &g_tmp[row*DD], sc, bb, &g_seq[row*DD]);
}

// ---------------- fused sparse attention ----------------
// Each row i attends to <= 11 columns: up to 5 intra-scale (|d|<=2),
// up to 5 children (window-4 + remainder on last parent), 1 parent.
// exp(-1e9 - max) == 0 in fp32, so this equals the dense masked softmax.
#define MAXN 12
__global__ __launch_bounds__(256)
void attn_kernel() {
    int i = blockIdx.x, b = blockIdx.y;
    __shared__ int s_nbr[MAXN];
    __shared__ int s_nn;
    int tid = threadIdx.x;
    if (tid == 0) {
        const int starts[5] = {0, 1025, 1281, 1345, 1361};
        int li = (i < 1025) ? 0 : (i < 1281) ? 1 : (i < 1345) ? 2 : 3;
        int s = starts[li], e = starts[li+1];
        int nn = 0;
        int jlo = (i - 2 > s) ? i - 2 : s;
        int jhi = (i + 2 < e - 1) ? i + 2 : e - 1;
        for (int j = jlo; j <= jhi; j++) s_nbr[nn++] = j;
        if (li > 0) {
            int ps = starts[li-1];
            int qq = i - s;
            int lo = ps + qq * 4;
            int hi = (i == e - 1) ? s : ps + (qq + 1) * 4;
            for (int j = lo; j < hi; j++) s_nbr[nn++] = j;
        }
        if (li < 3) {
            int su = starts[li+1];
            int szu = starts[li+2] - su;
            int qq = (i - s) / 4;
            s_nbr[nn++] = su + ((qq < szu - 1) ? qq : szu - 1);
        }
        s_nn = nn;
        for (int j = nn; j < MAXN; j++) s_nbr[j] = i;  // safe dummy
    }
    __syncthreads();
    int nn = s_nn;
    int h = tid >> 5, lane = tid & 31;
    size_t rowbase = ((size_t)b*NT + i)*DD + h*64;
    float q0 = g_q[rowbase + lane];
    float q1 = g_q[rowbase + lane + 32];

    float dots[MAXN];
    #pragma unroll
    for (int jj = 0; jj < MAXN; jj++) {
        size_t kb = ((size_t)b*NT + s_nbr[jj])*DD + h*64;
        float p = q0 * g_k[kb + lane] + q1 * g_k[kb + lane + 32];
        #pragma unroll
        for (int o = 16; o; o >>= 1) p += __shfl_xor_sync(0xffffffffu, p, o);
        dots[jj] = (jj < nn) ? p * 0.125f : -1e30f;
    }
    float mx = -1e30f;
    #pragma unroll
    for (int jj = 0; jj < MAXN; jj++) mx = fmaxf(mx, dots[jj]);
    float sum = 0.f;
    #pragma unroll
    for (int jj = 0; jj < MAXN; jj++) { dots[jj] = expf(dots[jj] - mx); sum += dots[jj]; }
    float inv = 1.f / sum;
    float o0 = 0.f, o1 = 0.f;
    #pragma unroll
    for (int jj = 0; jj < MAXN; jj++) {
        size_t vb = ((size_t)b*NT + s_nbr[jj])*DD + h*64;
        float w = dots[jj] * inv;
        o0 += w * g_v[vb + lane];
        o1 += w * g_v[vb + lane + 32];
    }
    g_o[rowbase + lane]      = o0;
    g_o[rowbase + lane + 32] = o1;
}

// ---------------- gather + prediction head ----------------
__global__ void pred_kernel(const float* __restrict__ pw, float* __restrict__ out) {
    int b = blockIdx.x;
    __shared__ float gv[2048];
    const int rows[4] = {1024, 1280, 1344, 1360};
    int tid = threadIdx.x;   // 672
    for (int r = tid; r < 2048; r += 672) {
        int wch = r >> 9, d = r & 511;
        gv[r] = g_seq[((size_t)b*NT + rows[wch])*DD + d];
    }
    __syncthreads();
    float acc = 0.f;
    for (int r = 0; r < 2048; r++) acc += gv[r] * pw[(size_t)r*672 + tid];
    out[(size_t)b*672 + tid] = acc;
}

// ---------------- host ----------------
static void launch_sgemm(const float* A, const float* Bm, const float* bias,
                         float* C, int M, int N, int K, int act) {
    dim3 grid(N / 128, (M + 127) / 128);
    if (act == 1) sgemm_kernel<1><<<grid, 256>>>(A, Bm, bias, C, M, N, K);
    else          sgemm_kernel<0><<<grid, 256>>>(A, Bm, bias, C, M, N, K);
}

extern "C" void kernel_launch(void* const* d_in, const int* in_sizes, int n_in,
                              void* d_out, int out_size) {
    const float* x_enc   = (const float*)d_in[0];
    const float* xme     = (const float*)d_in[1];
    // d_in[2] = x_dec (unused by the model math)
    const float* xmd     = (const float*)d_in[3];
    const float* token_w = (const float*)d_in[4];
    const float* token_b = (const float*)d_in[5];
    const float* temp_w  = (const float*)d_in[6];
    const float* temp_b  = (const float*)d_in[7];
    const float* down_w  = (const float*)d_in[8];
    const float* down_b  = (const float*)d_in[9];
    const float* conv_w  = (const float*)d_in[10];
    const float* conv_b  = (const float*)d_in[11];
    const float* up_w    = (const float*)d_in[12];
    const float* up_b    = (const float*)d_in[13];
    const float* cln_s   = (const float*)d_in[14];
    const float* cln_b   = (const float*)d_in[15];
    const float* Wq      = (const float*)d_in[16];
    const float* Wk      = (const float*)d_in[17];
    const float* Wv      = (const float*)d_in[18];
    const float* Wo      = (const float*)d_in[19];
    const float* bo      = (const float*)d_in[20];
    const float* ln1_s   = (const float*)d_in[21];
    const float* ln1_b   = (const float*)d_in[22];
    const float* W1      = (const float*)d_in[23];
    const float* b1      = (const float*)d_in[24];
    const float* W2      = (const float*)d_in[25];
    const float* b2      = (const float*)d_in[26];
    const float* ln2_s   = (const float*)d_in[27];
    const float* ln2_b   = (const float*)d_in[28];
    const float* pred_w  = (const float*)d_in[29];

    float *emb, *d0, *cc, *pyr, *seq, *q, *k, *v, *o, *tmp, *ffn;
    cudaGetSymbolAddress((void**)&emb, g_emb);
    cudaGetSymbolAddress((void**)&d0,  g_d0);
    cudaGetSymbolAddress((void**)&cc,  g_cc);
    cudaGetSymbolAddress((void**)&pyr, g_pyr);
    cudaGetSymbolAddress((void**)&seq, g_seq);
    cudaGetSymbolAddress((void**)&q,   g_q);
    cudaGetSymbolAddress((void**)&k,   g_k);
    cudaGetSymbolAddress((void**)&v,   g_v);
    cudaGetSymbolAddress((void**)&o,   g_o);
    cudaGetSymbolAddress((void**)&tmp, g_tmp);
    cudaGetSymbolAddress((void**)&ffn, g_ffn);

    // 1) embedding (token conv + PE + temporal)
    embed_kernel<<<dim3(LL, BB), 128>>>(x_enc, xme, xmd, token_w, token_b, temp_w, temp_b);

    // 2) bottleneck down-projection: (B*L,512)@(512,128)
    launch_sgemm(emb, down_w, down_b, d0, BB*LL, 128, DD, 0);

    // 3) pyramid convs (stride4/k4 + ELU), chained into g_cc rows [0:256|256:320|320:336]
    conv_kernel<<<dim3(256, BB), 128>>>(d0, LL, 0,   conv_w,               conv_b,       cc, 0);
    conv_kernel<<<dim3(64,  BB), 128>>>(cc, 336, 0,  conv_w + 128*128*4,   conv_b + 128, cc, 256);
    conv_kernel<<<dim3(16,  BB), 128>>>(cc, 336, 256,conv_w + 2*128*128*4, conv_b + 256, cc, 320);

    // 4) up-projection: (B*336,128)@(128,512)
    launch_sgemm(cc, up_w, up_b, pyr, BB*336, DD, 128, 0);

    // 5) concat + LayerNorm -> seq
    concat_ln_kernel<<<MROWS, 256>>>(cln_s, cln_b);

    // 6) encoder layers
    for (int i = 0; i < 4; i++) {
        const size_t wofs = (size_t)i * DD * DD;
        launch_sgemm(seq, Wq + wofs, nullptr, q, MROWS, DD, DD, 0);
        launch_sgemm(seq, Wk + wofs, nullptr, k, MROWS, DD, DD, 0);
        launch_sgemm(seq, Wv + wofs, nullptr, v, MROWS, DD, DD, 0);

        attn_kernel<<<dim3(NT, BB), 256>>>();

        launch_sgemm(o, Wo + wofs, bo + i*DD, tmp, MROWS, DD, DD, 0);
        add_ln_kernel<<<MROWS, 256>>>(ln1_s + i*DD, ln1_b + i*DD);

        launch_sgemm(seq, W1 + (size_t)i*DD*DFF, b1 + i*DFF, ffn, MROWS, DFF, DD, 1);
        launch_sgemm(ffn, W2 + (size_t)i*DFF*DD, b2 + i*DD, tmp, MROWS, DD, DFF, 0);
        add_ln_kernel<<<MROWS, 256>>>(ln2_s + i*DD, ln2_b + i*DD);
    }

    // 7) gather pyramid nodes of the last step + prediction head
    pred_kernel<<<BB, 672>>>(pred_w, (float*)d_out);
}

// round 4
// speedup vs baseline: 1.7450x; 1.1539x over previous
#include <cuda_runtime.h>
#include <math.h>

#define BB 4
#define LL 1025
#define NT 1361
#define DD 512
#define HH 8
#define DFF 2048
#define MROWS (BB*NT)         // 5444

// ---------------- scratch (static device allocations) ----------------
__device__ float g_emb[BB*LL*DD];
__device__ float g_d0 [BB*LL*128];
__device__ float g_cc [BB*336*128];
__device__ float g_pyr[BB*336*DD];
__device__ float g_seq[BB*NT*DD];
__device__ float g_qkv[BB*NT*1536];
__device__ float g_o  [BB*NT*DD];
__device__ float g_tmp[BB*NT*DD];
__device__ float g_ffn[BB*NT*DFF];
__device__ float g_wqkv[4*512*1536];

// ---------------- embedding ----------------
__global__ void embed_kernel(const float* __restrict__ x_enc,
                             const float* __restrict__ xme,
                             const float* __restrict__ xmd,
                             const float* __restrict__ tw,
                             const float* __restrict__ tb,
                             const float* __restrict__ tempw,
                             const float* __restrict__ tempb) {
    int t = blockIdx.x, b = blockIdx.y;
    __shared__ float xv[3][7];
    __shared__ float xm[4];
    int tid = threadIdx.x;   // 128
    if (tid < 21) {
        int k = tid / 7, i = tid % 7;
        int r = t - 1 + k;
        int rr = (r + 1025) % 1025;
        float val = 0.f;
        if (rr < 1024) val = x_enc[((size_t)b*1024 + rr)*7 + i];
        xv[k][i] = val;
    }
    if (tid >= 32 && tid < 36) {
        int m = tid - 32;
        xm[m] = (t < 1024) ? xme[((size_t)b*1024 + t)*4 + m]
                           : xmd[((size_t)b*96)*4 + m];
    }
    __syncthreads();
    for (int d = tid; d < DD; d += 128) {
        float acc = tb[d];
        #pragma unroll
        for (int i = 0; i < 7; i++)
            #pragma unroll
            for (int k = 0; k < 3; k++)
                acc += xv[k][i] * tw[(d*7 + i)*3 + k];
        acc += tempb[d];
        #pragma unroll
        for (int m = 0; m < 4; m++) acc += xm[m] * tempw[m*DD + d];
        int m2 = d & ~1;
        float div = expf(-9.210340371976184f / 512.0f * (float)m2);
        float arg = (float)t * div;
        acc += (d & 1) ? cosf(arg) : sinf(arg);
        g_emb[((size_t)b*LL + t)*DD + d] = acc;
    }
}

// ---------------- QKV weight packing: [Wq|Wk|Wv] per layer ----------------
__global__ void pack_qkv(const float* __restrict__ Wq,
                         const float* __restrict__ Wk,
                         const float* __restrict__ Wv) {
    int idx = blockIdx.x * blockDim.x + threadIdx.x;   // over 4*512*128 float4s
    if (idx >= 4*512*128) return;
    int n4 = idx & 127;
    int k  = (idx >> 7) & 511;
    int l  = idx >> 16;
    size_t src = ((size_t)l*512 + k)*512;
    float4* dst = (float4*)(g_wqkv + ((size_t)l*512 + k)*1536);
    dst[n4]       = ((const float4*)(Wq + src))[n4];
    dst[128 + n4] = ((const float4*)(Wk + src))[n4];
    dst[256 + n4] = ((const float4*)(Wv + src))[n4];
}

// ---------------- double-buffered SGEMM: C = A(MxK)@B(KxN) [+bias][+gelu] ----
__device__ __forceinline__ float gelu_exact(float x) {
    return 0.5f * x * (1.0f + erff(x * 0.70710678118654752f));
}

template<int ACT>  // 0=none, 1=gelu
__global__ __launch_bounds__(256)
void sgemm_kernel(const float* __restrict__ A, const float* __restrict__ Bm,
                  const float* __restrict__ bias, float* __restrict__ C,
                  int M, int N, int K) {
    __shared__ float As[2][16][128];
    __shared__ float Bs[2][16][128];
    int tid = threadIdx.x;
    int bx = blockIdx.x, by = blockIdx.y;
    int tx = tid & 15, ty = tid >> 4;

    float acc[8][8];
    #pragma unroll
    for (int i = 0; i < 8; i++)
        #pragma unroll
        for (int j = 0; j < 8; j++) acc[i][j] = 0.f;

    // A: 128 rows x 16 k per tile; thread loads rows am, am+64 at k = ak..ak+3
    int am = tid >> 2;            // 0..63
    int ak = (tid & 3) * 4;       // 0,4,8,12
    int arow0 = by*128 + am;
    int arow1 = arow0 + 64;
    const float* Ap0 = A + (size_t)arow0 * K + ak;
    const float* Ap1 = A + (size_t)arow1 * K + ak;
    bool v0 = (arow0 < M), v1 = (arow1 < M);

    // B: 16 k x 128 n per tile; thread loads rows bk, bk+8 at n = bn..bn+3
    int bk = tid >> 5;            // 0..7
    int bn = (tid & 31) * 4;
    const float* Bp = Bm + (size_t)bk * N + bx*128 + bn;

    int nk = K >> 4;
    float4 a0, a1, b0, b1;

    // prologue: tile 0
    a0 = v0 ? *(const float4*)(Ap0) : make_float4(0,0,0,0);
    a1 = v1 ? *(const float4*)(Ap1) : make_float4(0,0,0,0);
    b0 = *(const float4*)(Bp);
    b1 = *(const float4*)(Bp + (size_t)8*N);
    As[0][ak+0][am] = a0.x; As[0][ak+1][am] = a0.y; As[0][ak+2][am] = a0.z; As[0][ak+3][am] = a0.w;
    As[0][ak+0][am+64] = a1.x; As[0][ak+1][am+64] = a1.y; As[0][ak+2][am+64] = a1.z; As[0][ak+3][am+64] = a1.w;
    *(float4*)&Bs[0][bk][bn] = b0;
    *(float4*)&Bs[0][bk+8][bn] = b1;
    __syncthreads();

    int buf = 0;
    for (int t = 1; t < nk; t++) {
        // prefetch tile t
        const float* ap0 = Ap0 + t*16;
        const float* ap1 = Ap1 + t*16;
        const float* bp  = Bp + (size_t)(t*16) * N;
        a0 = v0 ? *(const float4*)(ap0) : make_float4(0,0,0,0);
        a1 = v1 ? *(const float4*)(ap1) : make_float4(0,0,0,0);
        b0 = *(const float4*)(bp);
        b1 = *(const float4*)(bp + (size_t)8*N);

        // compute tile t-1
        #pragma unroll
        for (int kk = 0; kk < 16; kk++) {
            float ra[8], rb[8];
            *(float4*)&ra[0] = *(const float4*)&As[buf][kk][ty*8];
            *(float4*)&ra[4] = *(const float4*)&As[buf][kk][ty*8 + 4];
            *(float4*)&rb[0] = *(const float4*)&Bs[buf][kk][tx*8];
            *(float4*)&rb[4] = *(const float4*)&Bs[buf][kk][tx*8 + 4];
            #pragma unroll
            for (int i = 0; i < 8; i++)
                #pragma unroll
                for (int j = 0; j < 8; j++) acc[i][j] += ra[i]*rb[j];
        }

        int nb = buf ^ 1;
        As[nb][ak+0][am] = a0.x; As[nb][ak+1][am] = a0.y; As[nb][ak+2][am] = a0.z; As[nb][ak+3][am] = a0.w;
        As[nb][ak+0][am+64] = a1.x; As[nb][ak+1][am+64] = a1.y; As[nb][ak+2][am+64] = a1.z; As[nb][ak+3][am+64] = a1.w;
        *(float4*)&Bs[nb][bk][bn] = b0;
        *(float4*)&Bs[nb][bk+8][bn] = b1;
        __syncthreads();
        buf = nb;
    }

    // compute last tile
    #pragma unroll
    for (int kk = 0; kk < 16; kk++) {
        float ra[8], rb[8];
        *(float4*)&ra[0] = *(const float4*)&As[buf][kk][ty*8];
        *(float4*)&ra[4] = *(const float4*)&As[buf][kk][ty*8 + 4];
        *(float4*)&rb[0] = *(const float4*)&Bs[buf][kk][tx*8];
        *(float4*)&rb[4] = *(const float4*)&Bs[buf][kk][tx*8 + 4];
        #pragma unroll
        for (int i = 0; i < 8; i++)
            #pragma unroll
            for (int j = 0; j < 8; j++) acc[i][j] += ra[i]*rb[j];
    }

    #pragma unroll
    for (int i = 0; i < 8; i++) {
        int row = by*128 + ty*8 + i;
        if (row >= M) break;
        #pragma unroll
        for (int j = 0; j < 8; j += 4) {
            int col = bx*128 + tx*8 + j;
            float4 v;
            v.x = acc[i][j]; v.y = acc[i][j+1]; v.z = acc[i][j+2]; v.w = acc[i][j+3];
            if (bias) { v.x += bias[col]; v.y += bias[col+1]; v.z += bias[col+2]; v.w += bias[col+3]; }
            if (ACT == 1) { v.x = gelu_exact(v.x); v.y = gelu_exact(v.y); v.z = gelu_exact(v.z); v.w = gelu_exact(v.w); }
            *(float4*)&C[(size_t)row*N + col] = v;
        }
    }
}

// ---------------- conv (stride-4, kernel-4, ELU) ----------------
__global__ void conv_kernel(const float* __restrict__ in, int ibs, int inOff,
                            const float* __restrict__ w, const float* __restrict__ bias,
                            float* __restrict__ out, int outOff) {
    int t = blockIdx.x, b = blockIdx.y;
    int tid = threadIdx.x;   // 128 (= oc)
    __shared__ float si[512];
    const float* ip = in + (size_t)(b*ibs + inOff + 4*t) * 128;
    #pragma unroll
    for (int k = 0; k < 4; k++) si[k*128 + tid] = ip[k*128 + tid];
    __syncthreads();
    float acc = bias[tid];
    #pragma unroll 4
    for (int ic = 0; ic < 128; ic++) {
        float4 w4 = *(const float4*)&w[((size_t)tid*128 + ic)*4];
        acc += si[ic]*w4.x + si[128+ic]*w4.y + si[256+ic]*w4.z + si[384+ic]*w4.w;
    }
    acc = (acc > 0.f) ? acc : expm1f(acc);
    out[(size_t)(b*336 + outOff + t)*128 + tid] = acc;
}

// ---------------- layernorm core (512 wide, 256 threads) ----------------
__device__ __forceinline__ void ln_core(const float* __restrict__ x0,
                                        const float* __restrict__ x1,
                                        const float* __restrict__ sc,
                                        const float* __restrict__ bb,
                                        float* __restrict__ out) {
    __shared__ float red[8];
    int tid = threadIdx.x;
    float v0 = x0[tid]       + (x1 ? x1[tid]       : 0.f);
    float v1 = x0[tid + 256] + (x1 ? x1[tid + 256] : 0.f);
    float sum = v0 + v1;
    #pragma unroll
    for (int o = 16; o; o >>= 1) sum += __shfl_xor_sync(0xffffffffu, sum, o);
    if ((tid & 31) == 0) red[tid >> 5] = sum;
    __syncthreads();
    float tot = 0.f;
    #pragma unroll
    for (int w = 0; w < 8; w++) tot += red[w];
    float mean = tot * (1.0f/512.0f);
    __syncthreads();
    float d0 = v0 - mean, d1 = v1 - mean;
    float sq = d0*d0 + d1*d1;
    #pragma unroll
    for (int o = 16; o; o >>= 1) sq += __shfl_xor_sync(0xffffffffu, sq, o);
    if ((tid & 31) == 0) red[tid >> 5] = sq;
    __syncthreads();
    float vtot = 0.f;
    #pragma unroll
    for (int w = 0; w < 8; w++) vtot += red[w];
    float inv = rsqrtf(vtot * (1.0f/512.0f) + 1e-5f);
    out[tid]       = d0 * inv * sc[tid]       + bb[tid];
    out[tid + 256] = d1 * inv * sc[tid + 256] + bb[tid + 256];
}

__global__ void concat_ln_kernel(const float* __restrict__ sc, const float* __restrict__ bb) {
    int row = blockIdx.x;            // 0..5443
    int b = row / NT, n = row % NT;
    const float* src = (n < LL) ? &g_emb[((size_t)b*LL + n)*DD]
                                : &g_pyr[((size_t)b*336 + (n - LL))*DD];
    ln_core(src, nullptr, sc, bb, &g_seq[(size_t)row*DD]);
}

__global__ void add_ln_kernel(const float* __restrict__ sc, const float* __restrict__ bb) {
    size_t row = blockIdx.x;
    ln_core(&g_seq[row*DD], &g_tmp[row*DD], sc, bb, &g_seq[row*DD]);
}

// ---------------- fused sparse attention (reads packed qkv) ----------------
#define MAXN 12
__global__ __launch_bounds__(256)
void attn_kernel() {
    int i = blockIdx.x, b = blockIdx.y;
    __shared__ int s_nbr[MAXN];
    __shared__ int s_nn;
    int tid = threadIdx.x;
    if (tid == 0) {
        const int starts[5] = {0, 1025, 1281, 1345, 1361};
        int li = (i < 1025) ? 0 : (i < 1281) ? 1 : (i < 1345) ? 2 : 3;
        int s = starts[li], e = starts[li+1];
        int nn = 0;
        int jlo = (i - 2 > s) ? i - 2 : s;
        int jhi = (i + 2 < e - 1) ? i + 2 : e - 1;
        for (int j = jlo; j <= jhi; j++) s_nbr[nn++] = j;
        if (li > 0) {
            int ps = starts[li-1];
            int qq = i - s;
            int lo = ps + qq * 4;
            int hi = (i == e - 1) ? s : ps + (qq + 1) * 4;
            for (int j = lo; j < hi; j++) s_nbr[nn++] = j;
        }
        if (li < 3) {
            int su = starts[li+1];
            int szu = starts[li+2] - su;
            int qq = (i - s) / 4;
            s_nbr[nn++] = su + ((qq < szu - 1) ? qq : szu - 1);
        }
        s_nn = nn;
        for (int j = nn; j < MAXN; j++) s_nbr[j] = i;  // safe dummy
    }
    __syncthreads();
    int nn = s_nn;
    int h = tid >> 5, lane = tid & 31;
    size_t qbase = ((size_t)b*NT + i)*1536 + h*64;
    float q0 = g_qkv[qbase + lane];
    float q1 = g_qkv[qbase + lane + 32];

    float dots[MAXN];
    #pragma unroll
    for (int jj = 0; jj < MAXN; jj++) {
        size_t kb = ((size_t)b*NT + s_nbr[jj])*1536 + 512 + h*64;
        float p = q0 * g_qkv[kb + lane] + q1 * g_qkv[kb + lane + 32];
        #pragma unroll
        for (int o = 16; o; o >>= 1) p += __shfl_xor_sync(0xffffffffu, p, o);
        dots[jj] = (jj < nn) ? p * 0.125f : -1e30f;
    }
    float mx = -1e30f;
    #pragma unroll
    for (int jj = 0; jj < MAXN; jj++) mx = fmaxf(mx, dots[jj]);
    float sum = 0.f;
    #pragma unroll
    for (int jj = 0; jj < MAXN; jj++) { dots[jj] = expf(dots[jj] - mx); sum += dots[jj]; }
    float inv = 1.f / sum;
    float o0 = 0.f, o1 = 0.f;
    #pragma unroll
    for (int jj = 0; jj < MAXN; jj++) {
        size_t vb = ((size_t)b*NT + s_nbr[jj])*1536 + 1024 + h*64;
        float w = dots[jj] * inv;
        o0 += w * g_qkv[vb + lane];
        o1 += w * g_qkv[vb + lane + 32];
    }
    size_t obase = ((size_t)b*NT + i)*DD + h*64;
    g_o[obase + lane]      = o0;
    g_o[obase + lane + 32] = o1;
}

// ---------------- gather + prediction head ----------------
__global__ void pred_kernel(const float* __restrict__ pw, float* __restrict__ out) {
    int b = blockIdx.x;
    __shared__ float gv[2048];
    const int rows[4] = {1024, 1280, 1344, 1360};
    int tid = threadIdx.x;   // 672
    for (int r = tid; r < 2048; r += 672) {
        int wch = r >> 9, d = r & 511;
        gv[r] = g_seq[((size_t)b*NT + rows[wch])*DD + d];
    }
    __syncthreads();
    float acc = 0.f;
    for (int r = 0; r < 2048; r++) acc += gv[r] * pw[(size_t)r*672 + tid];
    out[(size_t)b*672 + tid] = acc;
}

// ---------------- host ----------------
static void launch_sgemm(const float* A, const float* Bm, const float* bias,
                         float* C, int M, int N, int K, int act) {
    dim3 grid(N / 128, (M + 127) / 128);
    if (act == 1) sgemm_kernel<1><<<grid, 256>>>(A, Bm, bias, C, M, N, K);
    else          sgemm_kernel<0><<<grid, 256>>>(A, Bm, bias, C, M, N, K);
}

extern "C" void kernel_launch(void* const* d_in, const int* in_sizes, int n_in,
                              void* d_out, int out_size) {
    const float* x_enc   = (const float*)d_in[0];
    const float* xme     = (const float*)d_in[1];
    // d_in[2] = x_dec (unused by the model math)
    const float* xmd     = (const float*)d_in[3];
    const float* token_w = (const float*)d_in[4];
    const float* token_b = (const float*)d_in[5];
    const float* temp_w  = (const float*)d_in[6];
    const float* temp_b  = (const float*)d_in[7];
    const float* down_w  = (const float*)d_in[8];
    const float* down_b  = (const float*)d_in[9];
    const float* conv_w  = (const float*)d_in[10];
    const float* conv_b  = (const float*)d_in[11];
    const float* up_w    = (const float*)d_in[12];
    const float* up_b    = (const float*)d_in[13];
    const float* cln_s   = (const float*)d_in[14];
    const float* cln_b   = (const float*)d_in[15];
    const float* Wq      = (const float*)d_in[16];
    const float* Wk      = (const float*)d_in[17];
    const float* Wv      = (const float*)d_in[18];
    const float* Wo      = (const float*)d_in[19];
    const float* bo      = (const float*)d_in[20];
    const float* ln1_s   = (const float*)d_in[21];
    const float* ln1_b   = (const float*)d_in[22];
    const float* W1      = (const float*)d_in[23];
    const float* b1      = (const float*)d_in[24];
    const float* W2      = (const float*)d_in[25];
    const float* b2      = (const float*)d_in[26];
    const float* ln2_s   = (const float*)d_in[27];
    const float* ln2_b   = (const float*)d_in[28];
    const float* pred_w  = (const float*)d_in[29];

    float *emb, *d0, *cc, *pyr, *seq, *qkv, *o, *tmp, *ffn, *wqkv;
    cudaGetSymbolAddress((void**)&emb, g_emb);
    cudaGetSymbolAddress((void**)&d0,  g_d0);
    cudaGetSymbolAddress((void**)&cc,  g_cc);
    cudaGetSymbolAddress((void**)&pyr, g_pyr);
    cudaGetSymbolAddress((void**)&seq, g_seq);
    cudaGetSymbolAddress((void**)&qkv, g_qkv);
    cudaGetSymbolAddress((void**)&o,   g_o);
    cudaGetSymbolAddress((void**)&tmp, g_tmp);
    cudaGetSymbolAddress((void**)&ffn, g_ffn);
    cudaGetSymbolAddress((void**)&wqkv, g_wqkv);

    // 0) pack QKV weights into [Wq|Wk|Wv] layout (all 4 layers)
    pack_qkv<<<(4*512*128 + 255)/256, 256>>>(Wq, Wk, Wv);

    // 1) embedding (token conv + PE + temporal)
    embed_kernel<<<dim3(LL, BB), 128>>>(x_enc, xme, xmd, token_w, token_b, temp_w, temp_b);

    // 2) bottleneck down-projection: (B*L,512)@(512,128)
    launch_sgemm(emb, down_w, down_b, d0, BB*LL, 128, DD, 0);

    // 3) pyramid convs (stride4/k4 + ELU), chained into g_cc rows [0:256|256:320|320:336]
    conv_kernel<<<dim3(256, BB), 128>>>(d0, LL, 0,   conv_w,               conv_b,       cc, 0);
    conv_kernel<<<dim3(64,  BB), 128>>>(cc, 336, 0,  conv_w + 128*128*4,   conv_b + 128, cc, 256);
    conv_kernel<<<dim3(16,  BB), 128>>>(cc, 336, 256,conv_w + 2*128*128*4, conv_b + 256, cc, 320);

    // 4) up-projection: (B*336,128)@(128,512)
    launch_sgemm(cc, up_w, up_b, pyr, BB*336, DD, 128, 0);

    // 5) concat + LayerNorm -> seq
    concat_ln_kernel<<<MROWS, 256>>>(cln_s, cln_b);

    // 6) encoder layers
    for (int i = 0; i < 4; i++) {
        // fused QKV: (5444,512)@(512,1536)
        launch_sgemm(seq, wqkv + (size_t)i*512*1536, nullptr, qkv, MROWS, 1536, DD, 0);

        attn_kernel<<<dim3(NT, BB), 256>>>();

        launch_sgemm(o, Wo + (size_t)i*DD*DD, bo + i*DD, tmp, MROWS, DD, DD, 0);
        add_ln_kernel<<<MROWS, 256>>>(ln1_s + i*DD, ln1_b + i*DD);

        launch_sgemm(seq, W1 + (size_t)i*DD*DFF, b1 + i*DFF, ffn, MROWS, DFF, DD, 1);
        launch_sgemm(ffn, W2 + (size_t)i*DFF*DD, b2 + i*DD, tmp, MROWS, DD, DFF, 0);
        add_ln_kernel<<<MROWS, 256>>>(ln2_s + i*DD, ln2_b + i*DD);
    }

    // 7) gather pyramid nodes of the last step + prediction head
    pred_kernel<<<BB, 672>>>(pred_w, (float*)d_out);
}

// round 5
// speedup vs baseline: 3.5631x; 2.0419x over previous
#include <cuda_runtime.h>
#include <math.h>
#include <stdint.h>

#define BB 4
#define LL 1025
#define NT 1361
#define DD 512
#define HH 8
#define DFF 2048
#define MROWS (BB*NT)         // 5444

// ---------------- scratch (static device allocations) ----------------
__device__ float g_emb[BB*LL*DD];
__device__ float g_d0 [BB*LL*128];
__device__ float g_cc [BB*336*128];
__device__ float g_pyr[BB*336*DD];
__device__ float g_seq[BB*NT*DD];
__device__ float g_qkv[BB*NT*1536];
__device__ float g_o  [BB*NT*DD];
__device__ float g_tmp[BB*NT*DD];
__device__ float g_ffn[BB*NT*DFF];
__device__ float g_wqkv[4*512*1536];

// ---------------- embedding ----------------
__global__ void embed_kernel(const float* __restrict__ x_enc,
                             const float* __restrict__ xme,
                             const float* __restrict__ xmd,
                             const float* __restrict__ tw,
                             const float* __restrict__ tb,
                             const float* __restrict__ tempw,
                             const float* __restrict__ tempb) {
    int t = blockIdx.x, b = blockIdx.y;
    __shared__ float xv[3][7];
    __shared__ float xm[4];
    int tid = threadIdx.x;   // 128
    if (tid < 21) {
        int k = tid / 7, i = tid % 7;
        int r = t - 1 + k;
        int rr = (r + 1025) % 1025;
        float val = 0.f;
        if (rr < 1024) val = x_enc[((size_t)b*1024 + rr)*7 + i];
        xv[k][i] = val;
    }
    if (tid >= 32 && tid < 36) {
        int m = tid - 32;
        xm[m] = (t < 1024) ? xme[((size_t)b*1024 + t)*4 + m]
                           : xmd[((size_t)b*96)*4 + m];
    }
    __syncthreads();
    for (int d = tid; d < DD; d += 128) {
        float acc = tb[d];
        #pragma unroll
        for (int i = 0; i < 7; i++)
            #pragma unroll
            for (int k = 0; k < 3; k++)
                acc += xv[k][i] * tw[(d*7 + i)*3 + k];
        acc += tempb[d];
        #pragma unroll
        for (int m = 0; m < 4; m++) acc += xm[m] * tempw[m*DD + d];
        int m2 = d & ~1;
        float div = expf(-9.210340371976184f / 512.0f * (float)m2);
        float arg = (float)t * div;
        acc += (d & 1) ? cosf(arg) : sinf(arg);
        g_emb[((size_t)b*LL + t)*DD + d] = acc;
    }
}

// ---------------- QKV weight packing: [Wq|Wk|Wv] per layer ----------------
__global__ void pack_qkv(const float* __restrict__ Wq,
                         const float* __restrict__ Wk,
                         const float* __restrict__ Wv) {
    int idx = blockIdx.x * blockDim.x + threadIdx.x;   // over 4*512*128 float4s
    if (idx >= 4*512*128) return;
    int n4 = idx & 127;
    int k  = (idx >> 7) & 511;
    int l  = idx >> 16;
    size_t src = ((size_t)l*512 + k)*512;
    float4* dst = (float4*)(g_wqkv + ((size_t)l*512 + k)*1536);
    dst[n4]       = ((const float4*)(Wq + src))[n4];
    dst[128 + n4] = ((const float4*)(Wk + src))[n4];
    dst[256 + n4] = ((const float4*)(Wv + src))[n4];
}

// ---------------- TF32 tensor-core GEMM ----------------
__device__ __forceinline__ float gelu_exact(float x) {
    return 0.5f * x * (1.0f + erff(x * 0.70710678118654752f));
}
__device__ __forceinline__ uint32_t f2tf(float x) {
    uint32_t r;
    asm("cvt.rna.tf32.f32 %0, %1;" : "=r"(r) : "f"(x));
    return r;
}
__device__ __forceinline__ void mma_tf32(float c[4], const uint32_t a[4], const uint32_t b[2]) {
    asm volatile(
        "mma.sync.aligned.m16n8k8.row.col.f32.tf32.tf32.f32 "
        "{%0,%1,%2,%3}, {%4,%5,%6,%7}, {%8,%9}, {%0,%1,%2,%3};\n"
        : "+f"(c[0]), "+f"(c[1]), "+f"(c[2]), "+f"(c[3])
        : "r"(a[0]), "r"(a[1]), "r"(a[2]), "r"(a[3]), "r"(b[0]), "r"(b[1]));
}

// C = A(MxK) @ B(KxN) [+bias][+gelu]; BM=BN=128, BK=16; 256 thr = 8 warps (4Mx2N)
template<int ACT>
__global__ __launch_bounds__(256)
void tgemm_kernel(const float* __restrict__ A, const float* __restrict__ Bm,
                  const float* __restrict__ bias, float* __restrict__ C,
                  int M, int N, int K) {
    __shared__ uint32_t As[2][16][132];
    __shared__ uint32_t Bs[2][16][132];
    int tid = threadIdx.x;
    int bx = blockIdx.x, by = blockIdx.y;
    int w = tid >> 5, lane = tid & 31;
    int wm = w & 3, wn = w >> 2;
    int g = lane >> 2, t4 = lane & 3;

    float c[2][8][4];
    #pragma unroll
    for (int mt = 0; mt < 2; mt++)
        #pragma unroll
        for (int nt = 0; nt < 8; nt++)
            #pragma unroll
            for (int r = 0; r < 4; r++) c[mt][nt][r] = 0.f;

    // A loader: rows am, am+64 at k=ak..ak+3 (store transposed k-major)
    int am = tid >> 2;            // 0..63
    int ak = (tid & 3) * 4;       // 0,4,8,12
    int arow0 = by*128 + am;
    int arow1 = arow0 + 64;
    const float* Ap0 = A + (size_t)arow0 * K + ak;
    const float* Ap1 = A + (size_t)arow1 * K + ak;
    bool v0 = (arow0 < M), v1 = (arow1 < M);

    // B loader: rows bk, bk+8 at n=bn..bn+3
    int bk = tid >> 5;            // 0..7
    int bn = (tid & 31) * 4;
    const float* Bp = Bm + (size_t)bk * N + bx*128 + bn;

    int nk = K >> 4;
    float4 a0, a1, b0, b1;

    // prologue
    a0 = v0 ? *(const float4*)(Ap0) : make_float4(0,0,0,0);
    a1 = v1 ? *(const float4*)(Ap1) : make_float4(0,0,0,0);
    b0 = *(const float4*)(Bp);
    b1 = *(const float4*)(Bp + (size_t)8*N);
    As[0][ak+0][am] = f2tf(a0.x); As[0][ak+1][am] = f2tf(a0.y);
    As[0][ak+2][am] = f2tf(a0.z); As[0][ak+3][am] = f2tf(a0.w);
    As[0][ak+0][am+64] = f2tf(a1.x); As[0][ak+1][am+64] = f2tf(a1.y);
    As[0][ak+2][am+64] = f2tf(a1.z); As[0][ak+3][am+64] = f2tf(a1.w);
    Bs[0][bk][bn+0] = f2tf(b0.x); Bs[0][bk][bn+1] = f2tf(b0.y);
    Bs[0][bk][bn+2] = f2tf(b0.z); Bs[0][bk][bn+3] = f2tf(b0.w);
    Bs[0][bk+8][bn+0] = f2tf(b1.x); Bs[0][bk+8][bn+1] = f2tf(b1.y);
    Bs[0][bk+8][bn+2] = f2tf(b1.z); Bs[0][bk+8][bn+3] = f2tf(b1.w);
    __syncthreads();

    int mb = wm*32 + g;
    int nb = wn*64 + g;
    int buf = 0;
    for (int tile = 1; tile < nk; tile++) {
        const float* ap0 = Ap0 + tile*16;
        const float* ap1 = Ap1 + tile*16;
        const float* bp  = Bp + (size_t)(tile*16) * N;
        a0 = v0 ? *(const float4*)(ap0) : make_float4(0,0,0,0);
        a1 = v1 ? *(const float4*)(ap1) : make_float4(0,0,0,0);
        b0 = *(const float4*)(bp);
        b1 = *(const float4*)(bp + (size_t)8*N);

        #pragma unroll
        for (int ks = 0; ks < 16; ks += 8) {
            uint32_t af[2][4], bf[8][2];
            #pragma unroll
            for (int mt = 0; mt < 2; mt++) {
                af[mt][0] = As[buf][ks+t4  ][mb + mt*16];
                af[mt][1] = As[buf][ks+t4  ][mb + mt*16 + 8];
                af[mt][2] = As[buf][ks+t4+4][mb + mt*16];
                af[mt][3] = As[buf][ks+t4+4][mb + mt*16 + 8];
            }
            #pragma unroll
            for (int nt = 0; nt < 8; nt++) {
                bf[nt][0] = Bs[buf][ks+t4  ][nb + nt*8];
                bf[nt][1] = Bs[buf][ks+t4+4][nb + nt*8];
            }
            #pragma unroll
            for (int mt = 0; mt < 2; mt++)
                #pragma unroll
                for (int nt = 0; nt < 8; nt++)
                    mma_tf32(c[mt][nt], af[mt], bf[nt]);
        }

        int nbuf = buf ^ 1;
        As[nbuf][ak+0][am] = f2tf(a0.x); As[nbuf][ak+1][am] = f2tf(a0.y);
        As[nbuf][ak+2][am] = f2tf(a0.z); As[nbuf][ak+3][am] = f2tf(a0.w);
        As[nbuf][ak+0][am+64] = f2tf(a1.x); As[nbuf][ak+1][am+64] = f2tf(a1.y);
        As[nbuf][ak+2][am+64] = f2tf(a1.z); As[nbuf][ak+3][am+64] = f2tf(a1.w);
        Bs[nbuf][bk][bn+0] = f2tf(b0.x); Bs[nbuf][bk][bn+1] = f2tf(b0.y);
        Bs[nbuf][bk][bn+2] = f2tf(b0.z); Bs[nbuf][bk][bn+3] = f2tf(b0.w);
        Bs[nbuf][bk+8][bn+0] = f2tf(b1.x); Bs[nbuf][bk+8][bn+1] = f2tf(b1.y);
        Bs[nbuf][bk+8][bn+2] = f2tf(b1.z); Bs[nbuf][bk+8][bn+3] = f2tf(b1.w);
        __syncthreads();
        buf = nbuf;
    }

    // last tile
    #pragma unroll
    for (int ks = 0; ks < 16; ks += 8) {
        uint32_t af[2][4], bf[8][2];
        #pragma unroll
        for (int mt = 0; mt < 2; mt++) {
            af[mt][0] = As[buf][ks+t4  ][mb + mt*16];
            af[mt][1] = As[buf][ks+t4  ][mb + mt*16 + 8];
            af[mt][2] = As[buf][ks+t4+4][mb + mt*16];
            af[mt][3] = As[buf][ks+t4+4][mb + mt*16 + 8];
        }
        #pragma unroll
        for (int nt = 0; nt < 8; nt++) {
            bf[nt][0] = Bs[buf][ks+t4  ][nb + nt*8];
            bf[nt][1] = Bs[buf][ks+t4+4][nb + nt*8];
        }
        #pragma unroll
        for (int mt = 0; mt < 2; mt++)
            #pragma unroll
            for (int nt = 0; nt < 8; nt++)
                mma_tf32(c[mt][nt], af[mt], bf[nt]);
    }

    // epilogue: c0,c1 -> (row, col..col+1), c2,c3 -> (row+8, ..)
    #pragma unroll
    for (int mt = 0; mt < 2; mt++) {
        int row0 = by*128 + wm*32 + mt*16 + g;
        int row1 = row0 + 8;
        #pragma unroll
        for (int nt = 0; nt < 8; nt++) {
            int col = bx*128 + wn*64 + nt*8 + 2*t4;
            float2 v0, v1;
            v0.x = c[mt][nt][0]; v0.y = c[mt][nt][1];
            v1.x = c[mt][nt][2]; v1.y = c[mt][nt][3];
            if (bias) {
                float bx0 = bias[col], bx1 = bias[col+1];
                v0.x += bx0; v0.y += bx1; v1.x += bx0; v1.y += bx1;
            }
            if (ACT == 1) {
                v0.x = gelu_exact(v0.x); v0.y = gelu_exact(v0.y);
                v1.x = gelu_exact(v1.x); v1.y = gelu_exact(v1.y);
            }
            if (row0 < M) *(float2*)&C[(size_t)row0*N + col] = v0;
            if (row1 < M) *(float2*)&C[(size_t)row1*N + col] = v1;
        }
    }
}

// ---------------- conv (stride-4, kernel-4, ELU) ----------------
__global__ void conv_kernel(const float* __restrict__ in, int ibs, int inOff,
                            const float* __restrict__ w, const float* __restrict__ bias,
                            float* __restrict__ out, int outOff) {
    int t = blockIdx.x, b = blockIdx.y;
    int tid = threadIdx.x;   // 128 (= oc)
    __shared__ float si[512];
    const float* ip = in + (size_t)(b*ibs + inOff + 4*t) * 128;
    #pragma unroll
    for (int k = 0; k < 4; k++) si[k*128 + tid] = ip[k*128 + tid];
    __syncthreads();
    float acc = bias[tid];
    #pragma unroll 4
    for (int ic = 0; ic < 128; ic++) {
        float4 w4 = *(const float4*)&w[((size_t)tid*128 + ic)*4];
        acc += si[ic]*w4.x + si[128+ic]*w4.y + si[256+ic]*w4.z + si[384+ic]*w4.w;
    }
    acc = (acc > 0.f) ? acc : expm1f(acc);
    out[(size_t)(b*336 + outOff + t)*128 + tid] = acc;
}

// ---------------- layernorm core (512 wide, 256 threads) ----------------
__device__ __forceinline__ void ln_core(const float* __restrict__ x0,
                                        const float* __restrict__ x1,
                                        const float* __restrict__ sc,
                                        const float* __restrict__ bb,
                                        float* __restrict__ out) {
    __shared__ float red[8];
    int tid = threadIdx.x;
    float v0 = x0[tid]       + (x1 ? x1[tid]       : 0.f);
    float v1 = x0[tid + 256] + (x1 ? x1[tid + 256] : 0.f);
    float sum = v0 + v1;
    #pragma unroll
    for (int o = 16; o; o >>= 1) sum += __shfl_xor_sync(0xffffffffu, sum, o);
    if ((tid & 31) == 0) red[tid >> 5] = sum;
    __syncthreads();
    float tot = 0.f;
    #pragma unroll
    for (int w = 0; w < 8; w++) tot += red[w];
    float mean = tot * (1.0f/512.0f);
    __syncthreads();
    float d0 = v0 - mean, d1 = v1 - mean;
    float sq = d0*d0 + d1*d1;
    #pragma unroll
    for (int o = 16; o; o >>= 1) sq += __shfl_xor_sync(0xffffffffu, sq, o);
    if ((tid & 31) == 0) red[tid >> 5] = sq;
    __syncthreads();
    float vtot = 0.f;
    #pragma unroll
    for (int w = 0; w < 8; w++) vtot += red[w];
    float inv = rsqrtf(vtot * (1.0f/512.0f) + 1e-5f);
    out[tid]       = d0 * inv * sc[tid]       + bb[tid];
    out[tid + 256] = d1 * inv * sc[tid + 256] + bb[tid + 256];
}

__global__ void concat_ln_kernel(const float* __restrict__ sc, const float* __restrict__ bb) {
    int row = blockIdx.x;            // 0..5443
    int b = row / NT, n = row % NT;
    const float* src = (n < LL) ? &g_emb[((size_t)b*LL + n)*DD]
                                : &g_pyr[((size_t)b*336 + (n - LL))*DD];
    ln_core(src, nullptr, sc, bb, &g_seq[(size_t)row*DD]);
}

__global__ void add_ln_kernel(const float* __restrict__ sc, const float* __restrict__ bb) {
    size_t row = blockIdx.x;
    ln_core(&g_seq[row*DD], &g_tmp[row*DD], sc, bb, &g_seq[row*DD]);
}

// ---------------- fused sparse attention (reads packed qkv) ----------------
#define MAXN 12
__global__ __launch_bounds__(256)
void attn_kernel() {
    int i = blockIdx.x, b = blockIdx.y;
    __shared__ int s_nbr[MAXN];
    __shared__ int s_nn;
    int tid = threadIdx.x;
    if (tid == 0) {
        const int starts[5] = {0, 1025, 1281, 1345, 1361};
        int li = (i < 1025) ? 0 : (i < 1281) ? 1 : (i < 1345) ? 2 : 3;
        int s = starts[li], e = starts[li+1];
        int nn = 0;
        int jlo = (i - 2 > s) ? i - 2 : s;
        int jhi = (i + 2 < e - 1) ? i + 2 : e - 1;
        for (int j = jlo; j <= jhi; j++) s_nbr[nn++] = j;
        if (li > 0) {
            int ps = starts[li-1];
            int qq = i - s;
            int lo = ps + qq * 4;
            int hi = (i == e - 1) ? s : ps + (qq + 1) * 4;
            for (int j = lo; j < hi; j++) s_nbr[nn++] = j;
        }
        if (li < 3) {
            int su = starts[li+1];
            int szu = starts[li+2] - su;
            int qq = (i - s) / 4;
            s_nbr[nn++] = su + ((qq < szu - 1) ? qq : szu - 1);
        }
        s_nn = nn;
        for (int j = nn; j < MAXN; j++) s_nbr[j] = i;  // safe dummy
    }
    __syncthreads();
    int nn = s_nn;
    int h = tid >> 5, lane = tid & 31;
    size_t qbase = ((size_t)b*NT + i)*1536 + h*64;
    float q0 = g_qkv[qbase + lane];
    float q1 = g_qkv[qbase + lane + 32];

    float dots[MAXN];
    #pragma unroll
    for (int jj = 0; jj < MAXN; jj++) {
        size_t kb = ((size_t)b*NT + s_nbr[jj])*1536 + 512 + h*64;
        float p = q0 * g_qkv[kb + lane] + q1 * g_qkv[kb + lane + 32];
        #pragma unroll
        for (int o = 16; o; o >>= 1) p += __shfl_xor_sync(0xffffffffu, p, o);
        dots[jj] = (jj < nn) ? p * 0.125f : -1e30f;
    }
    float mx = -1e30f;
    #pragma unroll
    for (int jj = 0; jj < MAXN; jj++) mx = fmaxf(mx, dots[jj]);
    float sum = 0.f;
    #pragma unroll
    for (int jj = 0; jj < MAXN; jj++) { dots[jj] = expf(dots[jj] - mx); sum += dots[jj]; }
    float inv = 1.f / sum;
    float o0 = 0.f, o1 = 0.f;
    #pragma unroll
    for (int jj = 0; jj < MAXN; jj++) {
        size_t vb = ((size_t)b*NT + s_nbr[jj])*1536 + 1024 + h*64;
        float w = dots[jj] * inv;
        o0 += w * g_qkv[vb + lane];
        o1 += w * g_qkv[vb + lane + 32];
    }
    size_t obase = ((size_t)b*NT + i)*DD + h*64;
    g_o[obase + lane]      = o0;
    g_o[obase + lane + 32] = o1;
}

// ---------------- gather + prediction head ----------------
__global__ void pred_kernel(const float* __restrict__ pw, float* __restrict__ out) {
    int b = blockIdx.x;
    __shared__ float gv[2048];
    const int rows[4] = {1024, 1280, 1344, 1360};
    int tid = threadIdx.x;   // 672
    for (int r = tid; r < 2048; r += 672) {
        int wch = r >> 9, d = r & 511;
        gv[r] = g_seq[((size_t)b*NT + rows[wch])*DD + d];
    }
    __syncthreads();
    float acc = 0.f;
    for (int r = 0; r < 2048; r++) acc += gv[r] * pw[(size_t)r*672 + tid];
    out[(size_t)b*672 + tid] = acc;
}

// ---------------- host ----------------
static void launch_gemm(const float* A, const float* Bm, const float* bias,
                        float* C, int M, int N, int K, int act) {
    dim3 grid(N / 128, (M + 127) / 128);
    if (act == 1) tgemm_kernel<1><<<grid, 256>>>(A, Bm, bias, C, M, N, K);
    else          tgemm_kernel<0><<<grid, 256>>>(A, Bm, bias, C, M, N, K);
}

extern "C" void kernel_launch(void* const* d_in, const int* in_sizes, int n_in,
                              void* d_out, int out_size) {
    const float* x_enc   = (const float*)d_in[0];
    const float* xme     = (const float*)d_in[1];
    // d_in[2] = x_dec (unused by the model math)
    const float* xmd     = (const float*)d_in[3];
    const float* token_w = (const float*)d_in[4];
    const float* token_b = (const float*)d_in[5];
    const float* temp_w  = (const float*)d_in[6];
    const float* temp_b  = (const float*)d_in[7];
    const float* down_w  = (const float*)d_in[8];
    const float* down_b  = (const float*)d_in[9];
    const float* conv_w  = (const float*)d_in[10];
    const float* conv_b  = (const float*)d_in[11];
    const float* up_w    = (const float*)d_in[12];
    const float* up_b    = (const float*)d_in[13];
    const float* cln_s   = (const float*)d_in[14];
    const float* cln_b   = (const float*)d_in[15];
    const float* Wq      = (const float*)d_in[16];
    const float* Wk      = (const float*)d_in[17];
    const float* Wv      = (const float*)d_in[18];
    const float* Wo      = (const float*)d_in[19];
    const float* bo      = (const float*)d_in[20];
    const float* ln1_s   = (const float*)d_in[21];
    const float* ln1_b   = (const float*)d_in[22];
    const float* W1      = (const float*)d_in[23];
    const float* b1      = (const float*)d_in[24];
    const float* W2      = (const float*)d_in[25];
    const float* b2      = (const float*)d_in[26];
    const float* ln2_s   = (const float*)d_in[27];
    const float* ln2_b   = (const float*)d_in[28];
    const float* pred_w  = (const float*)d_in[29];

    float *emb, *d0, *cc, *pyr, *seq, *qkv, *o, *tmp, *ffn, *wqkv;
    cudaGetSymbolAddress((void**)&emb, g_emb);
    cudaGetSymbolAddress((void**)&d0,  g_d0);
    cudaGetSymbolAddress((void**)&cc,  g_cc);
    cudaGetSymbolAddress((void**)&pyr, g_pyr);
    cudaGetSymbolAddress((void**)&seq, g_seq);
    cudaGetSymbolAddress((void**)&qkv, g_qkv);
    cudaGetSymbolAddress((void**)&o,   g_o);
    cudaGetSymbolAddress((void**)&tmp, g_tmp);
    cudaGetSymbolAddress((void**)&ffn, g_ffn);
    cudaGetSymbolAddress((void**)&wqkv, g_wqkv);

    // 0) pack QKV weights into [Wq|Wk|Wv] layout (all 4 layers)
    pack_qkv<<<(4*512*128 + 255)/256, 256>>>(Wq, Wk, Wv);

    // 1) embedding (token conv + PE + temporal)
    embed_kernel<<<dim3(LL, BB), 128>>>(x_enc, xme, xmd, token_w, token_b, temp_w, temp_b);

    // 2) bottleneck down-projection: (B*L,512)@(512,128)
    launch_gemm(emb, down_w, down_b, d0, BB*LL, 128, DD, 0);

    // 3) pyramid convs (stride4/k4 + ELU), chained into g_cc rows [0:256|256:320|320:336]
    conv_kernel<<<dim3(256, BB), 128>>>(d0, LL, 0,   conv_w,               conv_b,       cc, 0);
    conv_kernel<<<dim3(64,  BB), 128>>>(cc, 336, 0,  conv_w + 128*128*4,   conv_b + 128, cc, 256);
    conv_kernel<<<dim3(16,  BB), 128>>>(cc, 336, 256,conv_w + 2*128*128*4, conv_b + 256, cc, 320);

    // 4) up-projection: (B*336,128)@(128,512)
    launch_gemm(cc, up_w, up_b, pyr, BB*336, DD, 128, 0);

    // 5) concat + LayerNorm -> seq
    concat_ln_kernel<<<MROWS, 256>>>(cln_s, cln_b);

    // 6) encoder layers
    for (int i = 0; i < 4; i++) {
        // fused QKV: (5444,512)@(512,1536)
        launch_gemm(seq, wqkv + (size_t)i*512*1536, nullptr, qkv, MROWS, 1536, DD, 0);

        attn_kernel<<<dim3(NT, BB), 256>>>();

        launch_gemm(o, Wo + (size_t)i*DD*DD, bo + i*DD, tmp, MROWS, DD, DD, 0);
        add_ln_kernel<<<MROWS, 256>>>(ln1_s + i*DD, ln1_b + i*DD);

        launch_gemm(seq, W1 + (size_t)i*DD*DFF, b1 + i*DFF, ffn, MROWS, DFF, DD, 1);
        launch_gemm(ffn, W2 + (size_t)i*DFF*DD, b2 + i*DD, tmp, MROWS, DD, DFF, 0);
        add_ln_kernel<<<MROWS, 256>>>(ln2_s + i*DD, ln2_b + i*DD);
    }

    // 7) gather pyramid nodes of the last step + prediction head
    pred_kernel<<<BB, 672>>>(pred_w, (float*)d_out);
}

// round 7
// speedup vs baseline: 4.0301x; 1.1311x over previous
#include <cuda_runtime.h>
#include <math.h>
#include <stdint.h>

#define BB 4
#define LL 1025
#define NT 1361
#define DD 512
#define HH 8
#define DFF 2048
#define MROWS (BB*NT)         // 5444

// ---------------- scratch (static device allocations) ----------------
__device__ float g_emb [BB*LL*DD];
__device__ float g_d0  [BB*LL*128];
__device__ float g_cc  [BB*336*128];
__device__ float g_pyr [BB*336*DD];
__device__ float g_seq [BB*NT*DD];
__device__ float g_seqr[BB*NT*DD];      // tf32-rounded copy (GEMM A operand)
__device__ float g_qkv [BB*NT*1536];
__device__ float g_o   [BB*NT*DD];      // tf32-rounded at producer
__device__ float g_tmp [BB*NT*DD];
__device__ float g_ffn [BB*NT*DFF];     // tf32-rounded at producer (W1 epilogue)
// tf32-rounded weight packs (original [K][N] layout)
__device__ float g_wqkv[4*512*1536];
__device__ float g_wo  [4*512*512];
__device__ float g_w1  [4*512*2048];
__device__ float g_w2  [4*2048*512];

// ---------------- helpers ----------------
__device__ __forceinline__ uint32_t f2tf(float x) {
    uint32_t r;
    asm("cvt.rna.tf32.f32 %0, %1;" : "=r"(r) : "f"(x));
    return r;
}
__device__ __forceinline__ float f2tf_f(float x) { return __uint_as_float(f2tf(x)); }
__device__ __forceinline__ float gelu_exact(float x) {
    return 0.5f * x * (1.0f + erff(x * 0.70710678118654752f));
}
__device__ __forceinline__ void mma_tf32(float c[4], const uint32_t a[4], const uint32_t b[2]) {
    asm volatile(
        "mma.sync.aligned.m16n8k8.row.col.f32.tf32.tf32.f32 "
        "{%0,%1,%2,%3}, {%4,%5,%6,%7}, {%8,%9}, {%0,%1,%2,%3};\n"
        : "+f"(c[0]), "+f"(c[1]), "+f"(c[2]), "+f"(c[3])
        : "r"(a[0]), "r"(a[1]), "r"(a[2]), "r"(a[3]), "r"(b[0]), "r"(b[1]));
}

// ---------------- weight rounding packs ----------------
__global__ void pack_qkv(const float* __restrict__ Wq,
                         const float* __restrict__ Wk,
                         const float* __restrict__ Wv) {
    int idx = blockIdx.x * blockDim.x + threadIdx.x;   // over 4*512*128 float4s
    if (idx >= 4*512*128) return;
    int n4 = idx & 127;
    int k  = (idx >> 7) & 511;
    int l  = idx >> 16;
    size_t src = ((size_t)l*512 + k)*512;
    float4 q = ((const float4*)(Wq + src))[n4];
    float4 kk = ((const float4*)(Wk + src))[n4];
    float4 v = ((const float4*)(Wv + src))[n4];
    q.x=f2tf_f(q.x); q.y=f2tf_f(q.y); q.z=f2tf_f(q.z); q.w=f2tf_f(q.w);
    kk.x=f2tf_f(kk.x); kk.y=f2tf_f(kk.y); kk.z=f2tf_f(kk.z); kk.w=f2tf_f(kk.w);
    v.x=f2tf_f(v.x); v.y=f2tf_f(v.y); v.z=f2tf_f(v.z); v.w=f2tf_f(v.w);
    float4* dst = (float4*)(g_wqkv + ((size_t)l*512 + k)*1536);
    dst[n4] = q; dst[128 + n4] = kk; dst[256 + n4] = v;
}
__global__ void round_copy(const float* __restrict__ in, float* __restrict__ out, int n4) {
    int i = blockIdx.x*blockDim.x + threadIdx.x;
    if (i >= n4) return;
    float4 v = ((const float4*)in)[i];
    v.x = f2tf_f(v.x); v.y = f2tf_f(v.y); v.z = f2tf_f(v.z); v.w = f2tf_f(v.w);
    ((float4*)out)[i] = v;
}

// ---------------- TF32 mma.sync GEMM: C = A(MxK)@B(KxN) [+bias][+gelu+round] -------
// BM=BN=128, BK=16; 256 thr = 8 warps (4M x 2N), warp tile 32x64.
// Smem stride 136 (mod 32 == 8) -> conflict-free fragment loads.
// RND=1: loader rounds inputs to tf32; RND=0: inputs pre-rounded (pure copy loader).
template<int ACT, int RND>
__global__ __launch_bounds__(256)
void tgemm_kernel(const float* __restrict__ A, const float* __restrict__ Bm,
                  const float* __restrict__ bias, float* __restrict__ C,
                  int M, int N, int K) {
    __shared__ uint32_t As[2][16][136];
    __shared__ uint32_t Bs[2][16][136];
    int tid = threadIdx.x;
    int bx = blockIdx.x, by = blockIdx.y;
    int w = tid >> 5, lane = tid & 31;
    int wm = w & 3, wn = w >> 2;
    int g = lane >> 2, t4 = lane & 3;

    float c[2][8][4];
    #pragma unroll
    for (int mt = 0; mt < 2; mt++)
        #pragma unroll
        for (int nt = 0; nt < 8; nt++)
            #pragma unroll
            for (int r = 0; r < 4; r++) c[mt][nt][r] = 0.f;

    int am = tid >> 2;
    int ak = (tid & 3) * 4;
    int arow0 = by*128 + am;
    int arow1 = arow0 + 64;
    const float* Ap0 = A + (size_t)arow0 * K + ak;
    const float* Ap1 = A + (size_t)arow1 * K + ak;
    bool v0 = (arow0 < M), v1 = (arow1 < M);

    int bk = tid >> 5;
    int bn = (tid & 31) * 4;
    const float* Bp = Bm + (size_t)bk * N + bx*128 + bn;

    int nk = K >> 4;
    float4 a0, a1, b0, b1;

    #define CVT(x) (RND ? f2tf(x) : __float_as_uint(x))
    #define STORE_TILE(B_) do { \
        As[B_][ak+0][am] = CVT(a0.x); As[B_][ak+1][am] = CVT(a0.y); \
        As[B_][ak+2][am] = CVT(a0.z); As[B_][ak+3][am] = CVT(a0.w); \
        As[B_][ak+0][am+64] = CVT(a1.x); As[B_][ak+1][am+64] = CVT(a1.y); \
        As[B_][ak+2][am+64] = CVT(a1.z); As[B_][ak+3][am+64] = CVT(a1.w); \
        Bs[B_][bk][bn+0] = CVT(b0.x); Bs[B_][bk][bn+1] = CVT(b0.y); \
        Bs[B_][bk][bn+2] = CVT(b0.z); Bs[B_][bk][bn+3] = CVT(b0.w); \
        Bs[B_][bk+8][bn+0] = CVT(b1.x); Bs[B_][bk+8][bn+1] = CVT(b1.y); \
        Bs[B_][bk+8][bn+2] = CVT(b1.z); Bs[B_][bk+8][bn+3] = CVT(b1.w); \
    } while(0)

    a0 = v0 ? *(const float4*)(Ap0) : make_float4(0,0,0,0);
    a1 = v1 ? *(const float4*)(Ap1) : make_float4(0,0,0,0);
    b0 = *(const float4*)(Bp);
    b1 = *(const float4*)(Bp + (size_t)8*N);
    STORE_TILE(0);
    __syncthreads();

    int mb = wm*32 + g;
    int nb = wn*64 + g;
    int buf = 0;
    for (int tile = 1; tile < nk; tile++) {
        const float* ap0 = Ap0 + tile*16;
        const float* ap1 = Ap1 + tile*16;
        const float* bp  = Bp + (size_t)(tile*16) * N;
        a0 = v0 ? *(const float4*)(ap0) : make_float4(0,0,0,0);
        a1 = v1 ? *(const float4*)(ap1) : make_float4(0,0,0,0);
        b0 = *(const float4*)(bp);
        b1 = *(const float4*)(bp + (size_t)8*N);

        #pragma unroll
        for (int ks = 0; ks < 16; ks += 8) {
            uint32_t af[2][4], bf[8][2];
            #pragma unroll
            for (int mt = 0; mt < 2; mt++) {
                af[mt][0] = As[buf][ks+t4  ][mb + mt*16];
                af[mt][1] = As[buf][ks+t4  ][mb + mt*16 + 8];
                af[mt][2] = As[buf][ks+t4+4][mb + mt*16];
                af[mt][3] = As[buf][ks+t4+4][mb + mt*16 + 8];
            }
            #pragma unroll
            for (int nt = 0; nt < 8; nt++) {
                bf[nt][0] = Bs[buf][ks+t4  ][nb + nt*8];
                bf[nt][1] = Bs[buf][ks+t4+4][nb + nt*8];
            }
            #pragma unroll
            for (int mt = 0; mt < 2; mt++)
                #pragma unroll
                for (int nt = 0; nt < 8; nt++)
                    mma_tf32(c[mt][nt], af[mt], bf[nt]);
        }

        int nbuf = buf ^ 1;
        STORE_TILE(nbuf);
        __syncthreads();
        buf = nbuf;
    }

    #pragma unroll
    for (int ks = 0; ks < 16; ks += 8) {
        uint32_t af[2][4], bf[8][2];
        #pragma unroll
        for (int mt = 0; mt < 2; mt++) {
            af[mt][0] = As[buf][ks+t4  ][mb + mt*16];
            af[mt][1] = As[buf][ks+t4  ][mb + mt*16 + 8];
            af[mt][2] = As[buf][ks+t4+4][mb + mt*16];
            af[mt][3] = As[buf][ks+t4+4][mb + mt*16 + 8];
        }
        #pragma unroll
        for (int nt = 0; nt < 8; nt++) {
            bf[nt][0] = Bs[buf][ks+t4  ][nb + nt*8];
            bf[nt][1] = Bs[buf][ks+t4+4][nb + nt*8];
        }
        #pragma unroll
        for (int mt = 0; mt < 2; mt++)
            #pragma unroll
            for (int nt = 0; nt < 8; nt++)
                mma_tf32(c[mt][nt], af[mt], bf[nt]);
    }
    #undef CVT
    #undef STORE_TILE

    #pragma unroll
    for (int mt = 0; mt < 2; mt++) {
        int row0 = by*128 + wm*32 + mt*16 + g;
        int row1 = row0 + 8;
        #pragma unroll
        for (int nt = 0; nt < 8; nt++) {
            int col = bx*128 + wn*64 + nt*8 + 2*t4;
            float2 v0o, v1o;
            v0o.x = c[mt][nt][0]; v0o.y = c[mt][nt][1];
            v1o.x = c[mt][nt][2]; v1o.y = c[mt][nt][3];
            if (bias) {
                float bx0 = bias[col], bx1 = bias[col+1];
                v0o.x += bx0; v0o.y += bx1; v1o.x += bx0; v1o.y += bx1;
            }
            if (ACT == 1) {   // gelu + round (output feeds next tf32 GEMM)
                v0o.x = f2tf_f(gelu_exact(v0o.x)); v0o.y = f2tf_f(gelu_exact(v0o.y));
                v1o.x = f2tf_f(gelu_exact(v1o.x)); v1o.y = f2tf_f(gelu_exact(v1o.y));
            }
            if (row0 < M) *(float2*)&C[(size_t)row0*N + col] = v0o;
            if (row1 < M) *(float2*)&C[(size_t)row1*N + col] = v1o;
        }
    }
}

// ---------------- embedding ----------------
__global__ void embed_kernel(const float* __restrict__ x_enc,
                             const float* __restrict__ xme,
                             const float* __restrict__ xmd,
                             const float* __restrict__ tw,
                             const float* __restrict__ tb,
                             const float* __restrict__ tempw,
                             const float* __restrict__ tempb) {
    int t = blockIdx.x, b = blockIdx.y;
    __shared__ float xv[3][7];
    __shared__ float xm[4];
    int tid = threadIdx.x;   // 128
    if (tid < 21) {
        int k = tid / 7, i = tid % 7;
        int r = t - 1 + k;
        int rr = (r + 1025) % 1025;
        float val = 0.f;
        if (rr < 1024) val = x_enc[((size_t)b*1024 + rr)*7 + i];
        xv[k][i] = val;
    }
    if (tid >= 32 && tid < 36) {
        int m = tid - 32;
        xm[m] = (t < 1024) ? xme[((size_t)b*1024 + t)*4 + m]
                           : xmd[((size_t)b*96)*4 + m];
    }
    __syncthreads();
    for (int d = tid; d < DD; d += 128) {
        float acc = tb[d];
        #pragma unroll
        for (int i = 0; i < 7; i++)
            #pragma unroll
            for (int k = 0; k < 3; k++)
                acc += xv[k][i] * tw[(d*7 + i)*3 + k];
        acc += tempb[d];
        #pragma unroll
        for (int m = 0; m < 4; m++) acc += xm[m] * tempw[m*DD + d];
        int m2 = d & ~1;
        float div = expf(-9.210340371976184f / 512.0f * (float)m2);
        float arg = (float)t * div;
        acc += (d & 1) ? cosf(arg) : sinf(arg);
        g_emb[((size_t)b*LL + t)*DD + d] = acc;
    }
}

// ---------------- conv (stride-4, kernel-4, ELU) ----------------
__global__ void conv_kernel(const float* __restrict__ in, int ibs, int inOff,
                            const float* __restrict__ w, const float* __restrict__ bias,
                            float* __restrict__ out, int outOff) {
    int t = blockIdx.x, b = blockIdx.y;
    int tid = threadIdx.x;   // 128 (= oc)
    __shared__ float si[512];
    const float* ip = in + (size_t)(b*ibs + inOff + 4*t) * 128;
    #pragma unroll
    for (int k = 0; k < 4; k++) si[k*128 + tid] = ip[k*128 + tid];
    __syncthreads();
    float acc = bias[tid];
    #pragma unroll 4
    for (int ic = 0; ic < 128; ic++) {
        float4 w4 = *(const float4*)&w[((size_t)tid*128 + ic)*4];
        acc += si[ic]*w4.x + si[128+ic]*w4.y + si[256+ic]*w4.z + si[384+ic]*w4.w;
    }
    acc = (acc > 0.f) ? acc : expm1f(acc);
    out[(size_t)(b*336 + outOff + t)*128 + tid] = acc;
}

// ---------------- layernorm (512 wide, 256 threads) + rounded copy ----------------
__device__ __forceinline__ void ln_core(const float* __restrict__ x0,
                                        const float* __restrict__ x1,
                                        const float* __restrict__ sc,
                                        const float* __restrict__ bb,
                                        float* __restrict__ out,
                                        float* __restrict__ out_r) {
    __shared__ float red[8];
    int tid = threadIdx.x;
    float v0 = x0[tid]       + (x1 ? x1[tid]       : 0.f);
    float v1 = x0[tid + 256] + (x1 ? x1[tid + 256] : 0.f);
    float sum = v0 + v1;
    #pragma unroll
    for (int o = 16; o; o >>= 1) sum += __shfl_xor_sync(0xffffffffu, sum, o);
    if ((tid & 31) == 0) red[tid >> 5] = sum;
    __syncthreads();
    float tot = 0.f;
    #pragma unroll
    for (int w = 0; w < 8; w++) tot += red[w];
    float mean = tot * (1.0f/512.0f);
    __syncthreads();
    float d0 = v0 - mean, d1 = v1 - mean;
    float sq = d0*d0 + d1*d1;
    #pragma unroll
    for (int o = 16; o; o >>= 1) sq += __shfl_xor_sync(0xffffffffu, sq, o);
    if ((tid & 31) == 0) red[tid >> 5] = sq;
    __syncthreads();
    float vtot = 0.f;
    #pragma unroll
    for (int w = 0; w < 8; w++) vtot += red[w];
    float inv = rsqrtf(vtot * (1.0f/512.0f) + 1e-5f);
    float o0 = d0 * inv * sc[tid]       + bb[tid];
    float o1 = d1 * inv * sc[tid + 256] + bb[tid + 256];
    out[tid]       = o0;
    out[tid + 256] = o1;
    out_r[tid]       = f2tf_f(o0);
    out_r[tid + 256] = f2tf_f(o1);
}

__global__ void concat_ln_kernel(const float* __restrict__ sc, const float* __restrict__ bb) {
    int row = blockIdx.x;
    int b = row / NT, n = row % NT;
    const float* src = (n < LL) ? &g_emb[((size_t)b*LL + n)*DD]
                                : &g_pyr[((size_t)b*336 + (n - LL))*DD];
    ln_core(src, nullptr, sc, bb, &g_seq[(size_t)row*DD], &g_seqr[(size_t)row*DD]);
}

__global__ void add_ln_kernel(const float* __restrict__ sc, const float* __restrict__ bb) {
    size_t row = blockIdx.x;
    ln_core(&g_seq[row*DD], &g_tmp[row*DD], sc, bb, &g_seq[row*DD], &g_seqr[row*DD]);
}

// ---------------- fused sparse attention (reads packed qkv, rounds output) ---------
#define MAXN 12
__global__ __launch_bounds__(256)
void attn_kernel() {
    int i = blockIdx.x, b = blockIdx.y;
    __shared__ int s_nbr[MAXN];
    __shared__ int s_nn;
    int tid = threadIdx.x;
    if (tid == 0) {
        const int starts[5] = {0, 1025, 1281, 1345, 1361};
        int li = (i < 1025) ? 0 : (i < 1281) ? 1 : (i < 1345) ? 2 : 3;
        int s = starts[li], e = starts[li+1];
        int nn = 0;
        int jlo = (i - 2 > s) ? i - 2 : s;
        int jhi = (i + 2 < e - 1) ? i + 2 : e - 1;
        for (int j = jlo; j <= jhi; j++) s_nbr[nn++] = j;
        if (li > 0) {
            int ps = starts[li-1];
            int qq = i - s;
            int lo = ps + qq * 4;
            int hi = (i == e - 1) ? s : ps + (qq + 1) * 4;
            for (int j = lo; j < hi; j++) s_nbr[nn++] = j;
        }
        if (li < 3) {
            int su = starts[li+1];
            int szu = starts[li+2] - su;
            int qq = (i - s) / 4;
            s_nbr[nn++] = su + ((qq < szu - 1) ? qq : szu - 1);
        }
        s_nn = nn;
        for (int j = nn; j < MAXN; j++) s_nbr[j] = i;
    }
    __syncthreads();
    int nn = s_nn;
    int h = tid >> 5, lane = tid & 31;
    size_t qbase = ((size_t)b*NT + i)*1536 + h*64;
    float q0 = g_qkv[qbase + lane];
    float q1 = g_qkv[qbase + lane + 32];

    float dots[MAXN];
    #pragma unroll
    for (int jj = 0; jj < MAXN; jj++) {
        size_t kb = ((size_t)b*NT + s_nbr[jj])*1536 + 512 + h*64;
        float p = q0 * g_qkv[kb + lane] + q1 * g_qkv[kb + lane + 32];
        #pragma unroll
        for (int o = 16; o; o >>= 1) p += __shfl_xor_sync(0xffffffffu, p, o);
        dots[jj] = (jj < nn) ? p * 0.125f : -1e30f;
    }
    float mx = -1e30f;
    #pragma unroll
    for (int jj = 0; jj < MAXN; jj++) mx = fmaxf(mx, dots[jj]);
    float sum = 0.f;
    #pragma unroll
    for (int jj = 0; jj < MAXN; jj++) { dots[jj] = expf(dots[jj] - mx); sum += dots[jj]; }
    float inv = 1.f / sum;
    float o0 = 0.f, o1 = 0.f;
    #pragma unroll
    for (int jj = 0; jj < MAXN; jj++) {
        size_t vb = ((size_t)b*NT + s_nbr[jj])*1536 + 1024 + h*64;
        float w = dots[jj] * inv;
        o0 += w * g_qkv[vb + lane];
        o1 += w * g_qkv[vb + lane + 32];
    }
    size_t obase = ((size_t)b*NT + i)*DD + h*64;
    g_o[obase + lane]      = f2tf_f(o0);   // feeds Wo GEMM only
    g_o[obase + lane + 32] = f2tf_f(o1);
}

// ---------------- gather + prediction head ----------------
__global__ void pred_kernel(const float* __restrict__ pw, float* __restrict__ out) {
    int b = blockIdx.x;
    __shared__ float gv[2048];
    const int rows[4] = {1024, 1280, 1344, 1360};
    int tid = threadIdx.x;   // 672
    for (int r = tid; r < 2048; r += 672) {
        int wch = r >> 9, d = r & 511;
        gv[r] = g_seq[((size_t)b*NT + rows[wch])*DD + d];
    }
    __syncthreads();
    float acc = 0.f;
    for (int r = 0; r < 2048; r++) acc += gv[r] * pw[(size_t)r*672 + tid];
    out[(size_t)b*672 + tid] = acc;
}

// ---------------- host ----------------
static void launch_gemm_rnd(const float* A, const float* Bm, const float* bias,
                            float* C, int M, int N, int K, int act) {
    dim3 grid(N / 128, (M + 127) / 128);
    if (act == 1) tgemm_kernel<1,1><<<grid, 256>>>(A, Bm, bias, C, M, N, K);
    else          tgemm_kernel<0,1><<<grid, 256>>>(A, Bm, bias, C, M, N, K);
}
static void launch_gemm_pre(const float* A, const float* Bm, const float* bias,
                            float* C, int M, int N, int K, int act) {
    dim3 grid(N / 128, (M + 127) / 128);
    if (act == 1) tgemm_kernel<1,0><<<grid, 256>>>(A, Bm, bias, C, M, N, K);
    else          tgemm_kernel<0,0><<<grid, 256>>>(A, Bm, bias, C, M, N, K);
}

extern "C" void kernel_launch(void* const* d_in, const int* in_sizes, int n_in,
                              void* d_out, int out_size) {
    const float* x_enc   = (const float*)d_in[0];
    const float* xme     = (const float*)d_in[1];
    // d_in[2] = x_dec (unused by the model math)
    const float* xmd     = (const float*)d_in[3];
    const float* token_w = (const float*)d_in[4];
    const float* token_b = (const float*)d_in[5];
    const float* temp_w  = (const float*)d_in[6];
    const float* temp_b  = (const float*)d_in[7];
    const float* down_w  = (const float*)d_in[8];
    const float* down_b  = (const float*)d_in[9];
    const float* conv_w  = (const float*)d_in[10];
    const float* conv_b  = (const float*)d_in[11];
    const float* up_w    = (const float*)d_in[12];
    const float* up_b    = (const float*)d_in[13];
    const float* cln_s   = (const float*)d_in[14];
    const float* cln_b   = (const float*)d_in[15];
    const float* Wq      = (const float*)d_in[16];
    const float* Wk      = (const float*)d_in[17];
    const float* Wv      = (const float*)d_in[18];
    const float* Wo      = (const float*)d_in[19];
    const float* bo      = (const float*)d_in[20];
    const float* ln1_s   = (const float*)d_in[21];
    const float* ln1_b   = (const float*)d_in[22];
    const float* W1      = (const float*)d_in[23];
    const float* b1      = (const float*)d_in[24];
    const float* W2      = (const float*)d_in[25];
    const float* b2      = (const float*)d_in[26];
    const float* ln2_s   = (const float*)d_in[27];
    const float* ln2_b   = (const float*)d_in[28];
    const float* pred_w  = (const float*)d_in[29];

    float *emb, *d0, *cc, *pyr, *seq, *seqr, *qkv, *o, *tmp, *ffn;
    float *wqkv, *wo, *w1, *w2;
    cudaGetSymbolAddress((void**)&emb,  g_emb);
    cudaGetSymbolAddress((void**)&d0,   g_d0);
    cudaGetSymbolAddress((void**)&cc,   g_cc);
    cudaGetSymbolAddress((void**)&pyr,  g_pyr);
    cudaGetSymbolAddress((void**)&seq,  g_seq);
    cudaGetSymbolAddress((void**)&seqr, g_seqr);
    cudaGetSymbolAddress((void**)&qkv,  g_qkv);
    cudaGetSymbolAddress((void**)&o,    g_o);
    cudaGetSymbolAddress((void**)&tmp,  g_tmp);
    cudaGetSymbolAddress((void**)&ffn,  g_ffn);
    cudaGetSymbolAddress((void**)&wqkv, g_wqkv);
    cudaGetSymbolAddress((void**)&wo,   g_wo);
    cudaGetSymbolAddress((void**)&w1,   g_w1);
    cudaGetSymbolAddress((void**)&w2,   g_w2);

    // 0) round+pack all encoder weights (tf32 pre-rounding)
    pack_qkv<<<(4*512*128 + 255)/256, 256>>>(Wq, Wk, Wv);
    round_copy<<<(4*512*512/4 + 255)/256, 256>>>(Wo, wo, 4*512*512/4);
    round_copy<<<(4*512*2048/4 + 255)/256, 256>>>(W1, w1, 4*512*2048/4);
    round_copy<<<(4*2048*512/4 + 255)/256, 256>>>(W2, w2, 4*2048*512/4);

    // 1) embedding (token conv + PE + temporal)
    embed_kernel<<<dim3(LL, BB), 128>>>(x_enc, xme, xmd, token_w, token_b, temp_w, temp_b);

    // 2) bottleneck down-projection (loader-rounded path)
    launch_gemm_rnd(emb, down_w, down_b, d0, BB*LL, 128, DD, 0);

    // 3) pyramid convs (stride4/k4 + ELU)
    conv_kernel<<<dim3(256, BB), 128>>>(d0, LL, 0,   conv_w,               conv_b,       cc, 0);
    conv_kernel<<<dim3(64,  BB), 128>>>(cc, 336, 0,  conv_w + 128*128*4,   conv_b + 128, cc, 256);
    conv_kernel<<<dim3(16,  BB), 128>>>(cc, 336, 256,conv_w + 2*128*128*4, conv_b + 256, cc, 320);

    // 4) up-projection (loader-rounded path)
    launch_gemm_rnd(cc, up_w, up_b, pyr, BB*336, DD, 128, 0);

    // 5) concat + LayerNorm -> seq (+ rounded copy)
    concat_ln_kernel<<<MROWS, 256>>>(cln_s, cln_b);

    // 6) encoder layers (pre-rounded operands, CVT-free GEMM loader)
    for (int i = 0; i < 4; i++) {
        launch_gemm_pre(seqr, wqkv + (size_t)i*512*1536, nullptr, qkv, MROWS, 1536, 512, 0);

        attn_kernel<<<dim3(NT, BB), 256>>>();

        launch_gemm_pre(o, wo + (size_t)i*DD*DD, bo + i*DD, tmp, MROWS, DD, DD, 0);
        add_ln_kernel<<<MROWS, 256>>>(ln1_s + i*DD, ln1_b + i*DD);

        launch_gemm_pre(seqr, w1 + (size_t)i*DD*DFF, b1 + i*DFF, ffn, MROWS, DFF, DD, 1);
        launch_gemm_pre(ffn, w2 + (size_t)i*DFF*DD, b2 + i*DD, tmp, MROWS, DD, DFF, 0);
        add_ln_kernel<<<MROWS, 256>>>(ln2_s + i*DD, ln2_b + i*DD);
    }

    // 7) gather pyramid nodes of the last step + prediction head
    pred_kernel<<<BB, 672>>>(pred_w, (float*)d_out);
}